// round 1
// baseline (speedup 1.0000x reference)
#include <cuda_runtime.h>
#include <math.h>

#define N_MAX 50000
#define E_MAX 800000
#define F_IN 128
#define HH 256           // HEADS*HID = 4*64
#define NEG_SLOPE 0.2f

// ---------------- scratch (static device, no allocation) ----------------
__device__ __align__(16) float g_hs1[(size_t)N_MAX * HH];
__device__ __align__(16) float g_hd1[(size_t)N_MAX * HH];
__device__ __align__(16) float g_h1 [(size_t)N_MAX * HH];
__device__ __align__(16) float2 g_hs2[N_MAX];
__device__ __align__(16) float2 g_hd2[N_MAX];
__device__ int g_deg[N_MAX];
__device__ int g_cursor[N_MAX];
__device__ int g_rowptr[N_MAX + 1];
__device__ int g_eidx[E_MAX];

__device__ __forceinline__ float lrelu(float x) {
    return x > 0.f ? x : NEG_SLOPE * x;
}

// ---------------- CSR build ----------------
__global__ void init_kernel(int n) {
    int i = blockIdx.x * blockDim.x + threadIdx.x;
    if (i < n) { g_deg[i] = 0; g_cursor[i] = 0; }
}

__global__ void count_kernel(const int* __restrict__ dst, int e) {
    int i = blockIdx.x * blockDim.x + threadIdx.x;
    if (i < e) atomicAdd(&g_deg[dst[i]], 1);
}

__global__ void scan_kernel(int n, int e) {
    __shared__ int sums[1024];
    int t = threadIdx.x;
    int chunk = (n + 1023) >> 10;
    int b = t * chunk;
    int en = min(b + chunk, n);
    int s = 0;
    for (int i = b; i < en; i++) s += g_deg[i];
    sums[t] = s;
    __syncthreads();
    // Hillis-Steele inclusive scan
    for (int off = 1; off < 1024; off <<= 1) {
        int v = 0;
        if (t >= off) v = sums[t - off];
        __syncthreads();
        if (t >= off) sums[t] += v;
        __syncthreads();
    }
    int run = (t == 0) ? 0 : sums[t - 1];
    for (int i = b; i < en; i++) { g_rowptr[i] = run; run += g_deg[i]; }
    if (t == 0) g_rowptr[n] = e;
}

__global__ void scatter_kernel(const int* __restrict__ dst, int e) {
    int i = blockIdx.x * blockDim.x + threadIdx.x;
    if (i < e) {
        int d = dst[i];
        int pos = g_rowptr[d] + atomicAdd(&g_cursor[d], 1);
        g_eidx[pos] = i;
    }
}

// ---------------- layer-1 GEMM: C = feat @ W + b, [n,128]x[128,256] ----------------
// BM=128, BN=128, BK=16, 256 threads, 8x8 microtile, double-buffered smem.
__global__ __launch_bounds__(256) void sgemm_kernel(
    const float* __restrict__ A,
    const float* __restrict__ Ws, const float* __restrict__ bs,
    const float* __restrict__ Wd, const float* __restrict__ bd,
    int n)
{
    const float* B    = blockIdx.z ? Wd : Ws;
    const float* bias = blockIdx.z ? bd : bs;
    float* C          = blockIdx.z ? g_hd1 : g_hs1;

    const int rowBase = blockIdx.y * 128;
    const int colBase = blockIdx.x * 128;

    __shared__ float As[2][16][128];
    __shared__ float Bs[2][16][128];

    const int tid = threadIdx.x;
    const int tx = tid & 15;
    const int ty = tid >> 4;

    float acc[8][8];
#pragma unroll
    for (int i = 0; i < 8; i++)
#pragma unroll
        for (int j = 0; j < 8; j++) acc[i][j] = 0.f;

    const int aRow0 = tid >> 2;            // 0..63
    const int aK0   = (tid & 3) << 2;      // 0,4,8,12
    const int bK0   = tid >> 5;            // 0..7
    const int bCol0 = (tid & 31) << 2;     // 0..124

    const int gr0 = rowBase + aRow0;
    const int gr1 = rowBase + aRow0 + 64;

    float4 ra0, ra1, rb0, rb1;

    // prefetch tile 0
    ra0 = (gr0 < n) ? *(const float4*)&A[(size_t)gr0 * F_IN + aK0] : make_float4(0, 0, 0, 0);
    ra1 = (gr1 < n) ? *(const float4*)&A[(size_t)gr1 * F_IN + aK0] : make_float4(0, 0, 0, 0);
    rb0 = *(const float4*)&B[(size_t)bK0 * HH + colBase + bCol0];
    rb1 = *(const float4*)&B[(size_t)(bK0 + 8) * HH + colBase + bCol0];

    As[0][aK0 + 0][aRow0] = ra0.x; As[0][aK0 + 1][aRow0] = ra0.y;
    As[0][aK0 + 2][aRow0] = ra0.z; As[0][aK0 + 3][aRow0] = ra0.w;
    As[0][aK0 + 0][aRow0 + 64] = ra1.x; As[0][aK0 + 1][aRow0 + 64] = ra1.y;
    As[0][aK0 + 2][aRow0 + 64] = ra1.z; As[0][aK0 + 3][aRow0 + 64] = ra1.w;
    *(float4*)&Bs[0][bK0][bCol0]     = rb0;
    *(float4*)&Bs[0][bK0 + 8][bCol0] = rb1;
    __syncthreads();

#pragma unroll
    for (int kt = 0; kt < 8; kt++) {
        const int cur = kt & 1;
        if (kt < 7) {
            const int kb = (kt + 1) * 16;
            ra0 = (gr0 < n) ? *(const float4*)&A[(size_t)gr0 * F_IN + kb + aK0] : make_float4(0, 0, 0, 0);
            ra1 = (gr1 < n) ? *(const float4*)&A[(size_t)gr1 * F_IN + kb + aK0] : make_float4(0, 0, 0, 0);
            rb0 = *(const float4*)&B[(size_t)(kb + bK0) * HH + colBase + bCol0];
            rb1 = *(const float4*)&B[(size_t)(kb + bK0 + 8) * HH + colBase + bCol0];
        }
#pragma unroll
        for (int k = 0; k < 16; k++) {
            float a[8], b[8];
            *(float4*)&a[0] = *(const float4*)&As[cur][k][ty * 8];
            *(float4*)&a[4] = *(const float4*)&As[cur][k][ty * 8 + 4];
            *(float4*)&b[0] = *(const float4*)&Bs[cur][k][tx * 8];
            *(float4*)&b[4] = *(const float4*)&Bs[cur][k][tx * 8 + 4];
#pragma unroll
            for (int i = 0; i < 8; i++)
#pragma unroll
                for (int j = 0; j < 8; j++) acc[i][j] += a[i] * b[j];
        }
        if (kt < 7) {
            const int nxt = cur ^ 1;
            As[nxt][aK0 + 0][aRow0] = ra0.x; As[nxt][aK0 + 1][aRow0] = ra0.y;
            As[nxt][aK0 + 2][aRow0] = ra0.z; As[nxt][aK0 + 3][aRow0] = ra0.w;
            As[nxt][aK0 + 0][aRow0 + 64] = ra1.x; As[nxt][aK0 + 1][aRow0 + 64] = ra1.y;
            As[nxt][aK0 + 2][aRow0 + 64] = ra1.z; As[nxt][aK0 + 3][aRow0 + 64] = ra1.w;
            *(float4*)&Bs[nxt][bK0][bCol0]     = rb0;
            *(float4*)&Bs[nxt][bK0 + 8][bCol0] = rb1;
            __syncthreads();
        }
    }

#pragma unroll
    for (int i = 0; i < 8; i++) {
        int gr = rowBase + ty * 8 + i;
        if (gr < n) {
#pragma unroll
            for (int j = 0; j < 8; j += 4) {
                int col = colBase + tx * 8 + j;
                float4 v;
                v.x = acc[i][j + 0] + bias[col + 0];
                v.y = acc[i][j + 1] + bias[col + 1];
                v.z = acc[i][j + 2] + bias[col + 2];
                v.w = acc[i][j + 3] + bias[col + 3];
                *(float4*)&C[(size_t)gr * HH + col] = v;
            }
        }
    }
}

// ---------------- layer-1 edge phase: one warp per dst node, online softmax ----------------
// lane l handles dims [l*8, l*8+8) of the 256-dim vector; head = l/8 (64 dims per head).
// 8-lane butterfly gives the per-head attention score.
__global__ __launch_bounds__(256) void edge1_kernel(const int* __restrict__ src,
                                                    const float* __restrict__ attn1,
                                                    int n)
{
    const int warp = (blockIdx.x * blockDim.x + threadIdx.x) >> 5;
    const int lane = threadIdx.x & 31;
    if (warp >= n) return;

    const float4* hdp = (const float4*)&g_hd1[(size_t)warp * HH + lane * 8];
    const float4 hd0 = hdp[0], hd1 = hdp[1];
    const float4* ap = (const float4*)(attn1 + lane * 8);
    const float4 a0 = __ldg(ap), a1 = __ldg(ap + 1);

    const int beg = g_rowptr[warp];
    const int end = g_rowptr[warp + 1];

    float m = __int_as_float(0xff800000);   // -inf
    float s = 0.f;
    float4 acc0 = make_float4(0, 0, 0, 0);
    float4 acc1 = make_float4(0, 0, 0, 0);

    for (int i = beg; i < end; i++) {
        const int e  = g_eidx[i];
        const int sv = __ldg(&src[e]);
        const float4* hp = (const float4*)&g_hs1[(size_t)sv * HH + lane * 8];
        const float4 h0 = __ldg(hp);
        const float4 h1 = __ldg(hp + 1);

        float p = lrelu(h0.x + hd0.x) * a0.x + lrelu(h0.y + hd0.y) * a0.y
                + lrelu(h0.z + hd0.z) * a0.z + lrelu(h0.w + hd0.w) * a0.w
                + lrelu(h1.x + hd1.x) * a1.x + lrelu(h1.y + hd1.y) * a1.y
                + lrelu(h1.z + hd1.z) * a1.z + lrelu(h1.w + hd1.w) * a1.w;
        p += __shfl_xor_sync(0xffffffffu, p, 4);
        p += __shfl_xor_sync(0xffffffffu, p, 2);
        p += __shfl_xor_sync(0xffffffffu, p, 1);

        const float nm  = fmaxf(m, p);
        const float fac = __expf(m - nm);   // 0 on first edge (m=-inf)
        const float w   = __expf(p - nm);
        s = s * fac + w;
        acc0.x = acc0.x * fac + w * h0.x;  acc0.y = acc0.y * fac + w * h0.y;
        acc0.z = acc0.z * fac + w * h0.z;  acc0.w = acc0.w * fac + w * h0.w;
        acc1.x = acc1.x * fac + w * h1.x;  acc1.y = acc1.y * fac + w * h1.y;
        acc1.z = acc1.z * fac + w * h1.z;  acc1.w = acc1.w * fac + w * h1.w;
        m = nm;
    }

    const float inv = (s > 0.f) ? (1.f / s) : 0.f;
    float o[8] = { acc0.x * inv, acc0.y * inv, acc0.z * inv, acc0.w * inv,
                   acc1.x * inv, acc1.y * inv, acc1.z * inv, acc1.w * inv };
#pragma unroll
    for (int j = 0; j < 8; j++)
        o[j] = (o[j] > 0.f) ? o[j] : expm1f(o[j]);   // ELU

    float4* outp = (float4*)&g_h1[(size_t)warp * HH + lane * 8];
    outp[0] = make_float4(o[0], o[1], o[2], o[3]);
    outp[1] = make_float4(o[4], o[5], o[6], o[7]);
}

// ---------------- layer-2 projections: one warp per node, [256]->2 (x2 matrices) ----------------
__global__ __launch_bounds__(256) void gemv2_kernel(const float* __restrict__ W2s,
                                                    const float* __restrict__ b2s,
                                                    const float* __restrict__ W2d,
                                                    const float* __restrict__ b2d,
                                                    int n)
{
    const int warp = (blockIdx.x * blockDim.x + threadIdx.x) >> 5;
    const int lane = threadIdx.x & 31;
    if (warp >= n) return;

    const float* x = &g_h1[(size_t)warp * HH + lane * 8];
    float s0 = 0.f, s1 = 0.f, d0 = 0.f, d1 = 0.f;
#pragma unroll
    for (int j = 0; j < 8; j++) {
        const float xv = x[j];
        const int dix = lane * 8 + j;
        const float2 ws = __ldg((const float2*)&W2s[dix * 2]);
        const float2 wd = __ldg((const float2*)&W2d[dix * 2]);
        s0 += xv * ws.x;  s1 += xv * ws.y;
        d0 += xv * wd.x;  d1 += xv * wd.y;
    }
#pragma unroll
    for (int off = 16; off > 0; off >>= 1) {
        s0 += __shfl_xor_sync(0xffffffffu, s0, off);
        s1 += __shfl_xor_sync(0xffffffffu, s1, off);
        d0 += __shfl_xor_sync(0xffffffffu, d0, off);
        d1 += __shfl_xor_sync(0xffffffffu, d1, off);
    }
    if (lane == 0) {
        g_hs2[warp] = make_float2(s0 + __ldg(&b2s[0]), s1 + __ldg(&b2s[1]));
        g_hd2[warp] = make_float2(d0 + __ldg(&b2d[0]), d1 + __ldg(&b2d[1]));
    }
}

// ---------------- layer-2 edge phase: one thread per dst node ----------------
__global__ void edge2_kernel(const int* __restrict__ src,
                             const float* __restrict__ attn2,
                             float* __restrict__ out, int n)
{
    const int node = blockIdx.x * blockDim.x + threadIdx.x;
    if (node >= n) return;

    const float2 hd = g_hd2[node];
    const float ax = __ldg(&attn2[0]);
    const float ay = __ldg(&attn2[1]);

    const int beg = g_rowptr[node];
    const int end = g_rowptr[node + 1];

    float m = __int_as_float(0xff800000);
    float s = 0.f, a0 = 0.f, a1 = 0.f;

    for (int i = beg; i < end; i++) {
        const int e  = g_eidx[i];
        const int sv = __ldg(&src[e]);
        const float2 hs = g_hs2[sv];
        const float p = lrelu(hs.x + hd.x) * ax + lrelu(hs.y + hd.y) * ay;
        const float nm  = fmaxf(m, p);
        const float fac = __expf(m - nm);
        const float w   = __expf(p - nm);
        s  = s  * fac + w;
        a0 = a0 * fac + w * hs.x;
        a1 = a1 * fac + w * hs.y;
        m = nm;
    }
    const float inv = (s > 0.f) ? (1.f / s) : 0.f;
    out[(size_t)node * 2 + 0] = a0 * inv;
    out[(size_t)node * 2 + 1] = a1 * inv;
}

// ---------------- launch ----------------
extern "C" void kernel_launch(void* const* d_in, const int* in_sizes, int n_in,
                              void* d_out, int out_size)
{
    const float* feat  = (const float*)d_in[0];
    const int*   src   = (const int*)  d_in[1];
    const int*   dst   = (const int*)  d_in[2];
    const float* W1s   = (const float*)d_in[3];
    const float* b1s   = (const float*)d_in[4];
    const float* W1d   = (const float*)d_in[5];
    const float* b1d   = (const float*)d_in[6];
    const float* attn1 = (const float*)d_in[7];
    const float* W2s   = (const float*)d_in[8];
    const float* b2s   = (const float*)d_in[9];
    const float* W2d   = (const float*)d_in[10];
    const float* b2d   = (const float*)d_in[11];
    const float* attn2 = (const float*)d_in[12];

    const int n = in_sizes[0] / F_IN;
    const int e = in_sizes[1];

    // CSR build
    init_kernel<<<(n + 255) / 256, 256>>>(n);
    count_kernel<<<(e + 255) / 256, 256>>>(dst, e);
    scan_kernel<<<1, 1024>>>(n, e);
    scatter_kernel<<<(e + 255) / 256, 256>>>(dst, e);

    // layer-1 projections (hs1, hd1)
    dim3 g1(2, (n + 127) / 128, 2);
    sgemm_kernel<<<g1, 256>>>(feat, W1s, b1s, W1d, b1d, n);

    // layer-1 attention + aggregation + ELU -> g_h1
    edge1_kernel<<<(n + 7) / 8, 256>>>(src, attn1, n);

    // layer-2 projections
    gemv2_kernel<<<(n + 7) / 8, 256>>>(W2s, b2s, W2d, b2d, n);

    // layer-2 attention + aggregation -> output [n,2]
    edge2_kernel<<<(n + 255) / 256, 256>>>(src, attn2, (float*)d_out, n);
}

// round 2
// speedup vs baseline: 1.0983x; 1.0983x over previous
#include <cuda_runtime.h>
#include <math.h>

#define N_MAX 50000
#define E_MAX 800000
#define F_IN 128
#define HH 256           // HEADS*HID = 4*64
#define NEG_SLOPE 0.2f

// ---------------- scratch (static device, no allocation) ----------------
__device__ __align__(16) float g_hs1[(size_t)N_MAX * HH];
__device__ __align__(16) float g_hd1[(size_t)N_MAX * HH];
__device__ __align__(16) float2 g_hs2[N_MAX];
__device__ __align__(16) float2 g_hd2[N_MAX];
__device__ int g_deg[N_MAX];
__device__ int g_cursor[N_MAX];
__device__ int g_rowptr[N_MAX + 1];
__device__ int g_srcs[E_MAX];     // src node id, grouped by dst (CSR adjacency)

__device__ __forceinline__ float lrelu(float x) {
    return x > 0.f ? x : NEG_SLOPE * x;
}

// ---------------- CSR build ----------------
__global__ void init_kernel(int n) {
    int i = blockIdx.x * blockDim.x + threadIdx.x;
    if (i < n) { g_deg[i] = 0; g_cursor[i] = 0; }
}

__global__ void count_kernel(const int* __restrict__ dst, int e) {
    int i = blockIdx.x * blockDim.x + threadIdx.x;
    if (i < e) atomicAdd(&g_deg[dst[i]], 1);
}

__global__ void scan_kernel(int n, int e) {
    __shared__ int sums[1024];
    int t = threadIdx.x;
    int chunk = (n + 1023) >> 10;
    int b = t * chunk;
    int en = min(b + chunk, n);
    int s = 0;
    for (int i = b; i < en; i++) s += g_deg[i];
    sums[t] = s;
    __syncthreads();
    for (int off = 1; off < 1024; off <<= 1) {
        int v = 0;
        if (t >= off) v = sums[t - off];
        __syncthreads();
        if (t >= off) sums[t] += v;
        __syncthreads();
    }
    int run = (t == 0) ? 0 : sums[t - 1];
    for (int i = b; i < en; i++) { g_rowptr[i] = run; run += g_deg[i]; }
    if (t == 0) g_rowptr[n] = e;
}

// scatter src node ids directly (no eidx indirection in the hot loops)
__global__ void scatter_kernel(const int* __restrict__ src,
                               const int* __restrict__ dst, int e) {
    int i = blockIdx.x * blockDim.x + threadIdx.x;
    if (i < e) {
        int d = dst[i];
        int pos = g_rowptr[d] + atomicAdd(&g_cursor[d], 1);
        g_srcs[pos] = src[i];
    }
}

// ---------------- layer-1 GEMM: C = feat @ W + b, [n,128]x[128,256] ----------------
// BM=128, BN=128, BK=16, 256 threads, 8x8 microtile, double-buffered smem.
__global__ __launch_bounds__(256) void sgemm_kernel(
    const float* __restrict__ A,
    const float* __restrict__ Ws, const float* __restrict__ bs,
    const float* __restrict__ Wd, const float* __restrict__ bd,
    int n)
{
    const float* B    = blockIdx.z ? Wd : Ws;
    const float* bias = blockIdx.z ? bd : bs;
    float* C          = blockIdx.z ? g_hd1 : g_hs1;

    const int rowBase = blockIdx.y * 128;
    const int colBase = blockIdx.x * 128;

    __shared__ float As[2][16][128];
    __shared__ float Bs[2][16][128];

    const int tid = threadIdx.x;
    const int tx = tid & 15;
    const int ty = tid >> 4;

    float acc[8][8];
#pragma unroll
    for (int i = 0; i < 8; i++)
#pragma unroll
        for (int j = 0; j < 8; j++) acc[i][j] = 0.f;

    const int aRow0 = tid >> 2;            // 0..63
    const int aK0   = (tid & 3) << 2;      // 0,4,8,12
    const int bK0   = tid >> 5;            // 0..7
    const int bCol0 = (tid & 31) << 2;     // 0..124

    const int gr0 = rowBase + aRow0;
    const int gr1 = rowBase + aRow0 + 64;

    float4 ra0, ra1, rb0, rb1;

    ra0 = (gr0 < n) ? *(const float4*)&A[(size_t)gr0 * F_IN + aK0] : make_float4(0, 0, 0, 0);
    ra1 = (gr1 < n) ? *(const float4*)&A[(size_t)gr1 * F_IN + aK0] : make_float4(0, 0, 0, 0);
    rb0 = *(const float4*)&B[(size_t)bK0 * HH + colBase + bCol0];
    rb1 = *(const float4*)&B[(size_t)(bK0 + 8) * HH + colBase + bCol0];

    As[0][aK0 + 0][aRow0] = ra0.x; As[0][aK0 + 1][aRow0] = ra0.y;
    As[0][aK0 + 2][aRow0] = ra0.z; As[0][aK0 + 3][aRow0] = ra0.w;
    As[0][aK0 + 0][aRow0 + 64] = ra1.x; As[0][aK0 + 1][aRow0 + 64] = ra1.y;
    As[0][aK0 + 2][aRow0 + 64] = ra1.z; As[0][aK0 + 3][aRow0 + 64] = ra1.w;
    *(float4*)&Bs[0][bK0][bCol0]     = rb0;
    *(float4*)&Bs[0][bK0 + 8][bCol0] = rb1;
    __syncthreads();

#pragma unroll
    for (int kt = 0; kt < 8; kt++) {
        const int cur = kt & 1;
        if (kt < 7) {
            const int kb = (kt + 1) * 16;
            ra0 = (gr0 < n) ? *(const float4*)&A[(size_t)gr0 * F_IN + kb + aK0] : make_float4(0, 0, 0, 0);
            ra1 = (gr1 < n) ? *(const float4*)&A[(size_t)gr1 * F_IN + kb + aK0] : make_float4(0, 0, 0, 0);
            rb0 = *(const float4*)&B[(size_t)(kb + bK0) * HH + colBase + bCol0];
            rb1 = *(const float4*)&B[(size_t)(kb + bK0 + 8) * HH + colBase + bCol0];
        }
#pragma unroll
        for (int k = 0; k < 16; k++) {
            float a[8], b[8];
            *(float4*)&a[0] = *(const float4*)&As[cur][k][ty * 8];
            *(float4*)&a[4] = *(const float4*)&As[cur][k][ty * 8 + 4];
            *(float4*)&b[0] = *(const float4*)&Bs[cur][k][tx * 8];
            *(float4*)&b[4] = *(const float4*)&Bs[cur][k][tx * 8 + 4];
#pragma unroll
            for (int i = 0; i < 8; i++)
#pragma unroll
                for (int j = 0; j < 8; j++) acc[i][j] += a[i] * b[j];
        }
        if (kt < 7) {
            const int nxt = cur ^ 1;
            As[nxt][aK0 + 0][aRow0] = ra0.x; As[nxt][aK0 + 1][aRow0] = ra0.y;
            As[nxt][aK0 + 2][aRow0] = ra0.z; As[nxt][aK0 + 3][aRow0] = ra0.w;
            As[nxt][aK0 + 0][aRow0 + 64] = ra1.x; As[nxt][aK0 + 1][aRow0 + 64] = ra1.y;
            As[nxt][aK0 + 2][aRow0 + 64] = ra1.z; As[nxt][aK0 + 3][aRow0 + 64] = ra1.w;
            *(float4*)&Bs[nxt][bK0][bCol0]     = rb0;
            *(float4*)&Bs[nxt][bK0 + 8][bCol0] = rb1;
            __syncthreads();
        }
    }

#pragma unroll
    for (int i = 0; i < 8; i++) {
        int gr = rowBase + ty * 8 + i;
        if (gr < n) {
#pragma unroll
            for (int j = 0; j < 8; j += 4) {
                int col = colBase + tx * 8 + j;
                float4 v;
                v.x = acc[i][j + 0] + bias[col + 0];
                v.y = acc[i][j + 1] + bias[col + 1];
                v.z = acc[i][j + 2] + bias[col + 2];
                v.w = acc[i][j + 3] + bias[col + 3];
                *(float4*)&C[(size_t)gr * HH + col] = v;
            }
        }
    }
}

// ---------------- layer-1 edge phase + fused ELU + layer-2 GEMV ----------------
// One warp per dst node. Lane l handles dims [l*8, l*8+8); head = l/8.
// Online (flash-style) softmax; software-pipelined gather of hs1 rows.
// Epilogue: ELU then project [256]->2 with both W2s/W2d via full-warp butterfly.
__global__ __launch_bounds__(256) void edge1_kernel(
    const float* __restrict__ attn1,
    const float* __restrict__ W2s, const float* __restrict__ b2s,
    const float* __restrict__ W2d, const float* __restrict__ b2d,
    int n)
{
    const int warp = (blockIdx.x * blockDim.x + threadIdx.x) >> 5;
    const int lane = threadIdx.x & 31;
    if (warp >= n) return;

    const float4* hdp = (const float4*)&g_hd1[(size_t)warp * HH + lane * 8];
    const float4 hd0 = hdp[0], hd1 = hdp[1];
    const float4* ap = (const float4*)(attn1 + lane * 8);
    const float4 a0 = __ldg(ap), a1 = __ldg(ap + 1);

    const int beg = g_rowptr[warp];
    const int cnt = g_rowptr[warp + 1] - beg;
    const int* sp = g_srcs + beg;

    float m = __int_as_float(0xff800000);   // -inf
    float s = 0.f;
    float4 acc0 = make_float4(0, 0, 0, 0);
    float4 acc1 = make_float4(0, 0, 0, 0);

    // software pipeline: next edge's hs row in flight while computing current
    float4 h0n = make_float4(0, 0, 0, 0), h1n = h0n;
    if (cnt > 0) {
        const int sv = __ldg(&sp[0]);
        const float4* hp = (const float4*)&g_hs1[(size_t)sv * HH + lane * 8];
        h0n = __ldg(hp);
        h1n = __ldg(hp + 1);
    }

    for (int k = 0; k < cnt; k++) {
        const float4 h0 = h0n, h1 = h1n;
        if (k + 1 < cnt) {
            const int sv = __ldg(&sp[k + 1]);
            const float4* hp = (const float4*)&g_hs1[(size_t)sv * HH + lane * 8];
            h0n = __ldg(hp);
            h1n = __ldg(hp + 1);
        }

        float p = lrelu(h0.x + hd0.x) * a0.x + lrelu(h0.y + hd0.y) * a0.y
                + lrelu(h0.z + hd0.z) * a0.z + lrelu(h0.w + hd0.w) * a0.w
                + lrelu(h1.x + hd1.x) * a1.x + lrelu(h1.y + hd1.y) * a1.y
                + lrelu(h1.z + hd1.z) * a1.z + lrelu(h1.w + hd1.w) * a1.w;
        p += __shfl_xor_sync(0xffffffffu, p, 4);
        p += __shfl_xor_sync(0xffffffffu, p, 2);
        p += __shfl_xor_sync(0xffffffffu, p, 1);

        const float nm  = fmaxf(m, p);
        const float fac = __expf(m - nm);   // 0 on first edge (m=-inf)
        const float w   = __expf(p - nm);
        s = s * fac + w;
        acc0.x = acc0.x * fac + w * h0.x;  acc0.y = acc0.y * fac + w * h0.y;
        acc0.z = acc0.z * fac + w * h0.z;  acc0.w = acc0.w * fac + w * h0.w;
        acc1.x = acc1.x * fac + w * h1.x;  acc1.y = acc1.y * fac + w * h1.y;
        acc1.z = acc1.z * fac + w * h1.z;  acc1.w = acc1.w * fac + w * h1.w;
        m = nm;
    }

    const float inv = (s > 0.f) ? (1.f / s) : 0.f;
    float o[8] = { acc0.x * inv, acc0.y * inv, acc0.z * inv, acc0.w * inv,
                   acc1.x * inv, acc1.y * inv, acc1.z * inv, acc1.w * inv };

    // fused: ELU + layer-2 projections ([256] -> 2, two weight matrices)
    float s0 = 0.f, s1 = 0.f, d0 = 0.f, d1 = 0.f;
#pragma unroll
    for (int j = 0; j < 8; j++) {
        const float oj = (o[j] > 0.f) ? o[j] : expm1f(o[j]);   // ELU
        const int dix = lane * 8 + j;
        const float2 ws = __ldg((const float2*)&W2s[dix * 2]);
        const float2 wd = __ldg((const float2*)&W2d[dix * 2]);
        s0 += oj * ws.x;  s1 += oj * ws.y;
        d0 += oj * wd.x;  d1 += oj * wd.y;
    }
#pragma unroll
    for (int off = 16; off > 0; off >>= 1) {
        s0 += __shfl_xor_sync(0xffffffffu, s0, off);
        s1 += __shfl_xor_sync(0xffffffffu, s1, off);
        d0 += __shfl_xor_sync(0xffffffffu, d0, off);
        d1 += __shfl_xor_sync(0xffffffffu, d1, off);
    }
    if (lane == 0) {
        g_hs2[warp] = make_float2(s0 + __ldg(&b2s[0]), s1 + __ldg(&b2s[1]));
        g_hd2[warp] = make_float2(d0 + __ldg(&b2d[0]), d1 + __ldg(&b2d[1]));
    }
}

// ---------------- layer-2 edge phase: one thread per dst node ----------------
__global__ void edge2_kernel(const float* __restrict__ attn2,
                             float* __restrict__ out, int n)
{
    const int node = blockIdx.x * blockDim.x + threadIdx.x;
    if (node >= n) return;

    const float2 hd = g_hd2[node];
    const float ax = __ldg(&attn2[0]);
    const float ay = __ldg(&attn2[1]);

    const int beg = g_rowptr[node];
    const int cnt = g_rowptr[node + 1] - beg;
    const int* sp = g_srcs + beg;

    float m = __int_as_float(0xff800000);
    float s = 0.f, a0 = 0.f, a1 = 0.f;

    float2 hn = make_float2(0, 0);
    if (cnt > 0) hn = __ldg(&g_hs2[__ldg(&sp[0])]);

    for (int k = 0; k < cnt; k++) {
        const float2 hs = hn;
        if (k + 1 < cnt) hn = __ldg(&g_hs2[__ldg(&sp[k + 1])]);

        const float p = lrelu(hs.x + hd.x) * ax + lrelu(hs.y + hd.y) * ay;
        const float nm  = fmaxf(m, p);
        const float fac = __expf(m - nm);
        const float w   = __expf(p - nm);
        s  = s  * fac + w;
        a0 = a0 * fac + w * hs.x;
        a1 = a1 * fac + w * hs.y;
        m = nm;
    }
    const float inv = (s > 0.f) ? (1.f / s) : 0.f;
    out[(size_t)node * 2 + 0] = a0 * inv;
    out[(size_t)node * 2 + 1] = a1 * inv;
}

// ---------------- launch ----------------
extern "C" void kernel_launch(void* const* d_in, const int* in_sizes, int n_in,
                              void* d_out, int out_size)
{
    const float* feat  = (const float*)d_in[0];
    const int*   src   = (const int*)  d_in[1];
    const int*   dst   = (const int*)  d_in[2];
    const float* W1s   = (const float*)d_in[3];
    const float* b1s   = (const float*)d_in[4];
    const float* W1d   = (const float*)d_in[5];
    const float* b1d   = (const float*)d_in[6];
    const float* attn1 = (const float*)d_in[7];
    const float* W2s   = (const float*)d_in[8];
    const float* b2s   = (const float*)d_in[9];
    const float* W2d   = (const float*)d_in[10];
    const float* b2d   = (const float*)d_in[11];
    const float* attn2 = (const float*)d_in[12];

    const int n = in_sizes[0] / F_IN;
    const int e = in_sizes[1];

    // CSR build (adjacency holds src node ids directly)
    init_kernel<<<(n + 255) / 256, 256>>>(n);
    count_kernel<<<(e + 255) / 256, 256>>>(dst, e);
    scan_kernel<<<1, 1024>>>(n, e);
    scatter_kernel<<<(e + 255) / 256, 256>>>(src, dst, e);

    // layer-1 projections (hs1, hd1)
    dim3 g1(2, (n + 127) / 128, 2);
    sgemm_kernel<<<g1, 256>>>(feat, W1s, b1s, W1d, b1d, n);

    // layer-1 attention + aggregation + ELU + layer-2 GEMV (fused)
    edge1_kernel<<<(n + 7) / 8, 256>>>(attn1, W2s, b2s, W2d, b2d, n);

    // layer-2 attention + aggregation -> output [n,2]
    edge2_kernel<<<(n + 255) / 256, 256>>>(attn2, (float*)d_out, n);
}

// round 4
// speedup vs baseline: 1.1215x; 1.0211x over previous
#include <cuda_runtime.h>
#include <math.h>

#define N_MAX 50000
#define E_MAX 800000
#define F_IN 128
#define HH 256           // HEADS*HID = 4*64
#define NEG_SLOPE 0.2f

// ---------------- scratch (static device, no allocation) ----------------
__device__ __align__(16) float g_hs1[(size_t)N_MAX * HH];
__device__ __align__(16) float g_hd1[(size_t)N_MAX * HH];
__device__ __align__(16) float2 g_hs2[N_MAX];
__device__ __align__(16) float2 g_hd2[N_MAX];
__device__ int g_deg[N_MAX];
__device__ int g_cursor[N_MAX];
__device__ int g_rowptr[N_MAX + 1];
__device__ int g_srcs[E_MAX];     // src node id, grouped by dst (CSR adjacency)

__device__ __forceinline__ float lrelu(float x) {
    return x > 0.f ? x : NEG_SLOPE * x;
}

// ---------------- CSR build ----------------
__global__ void init_kernel(int n) {
    int i = blockIdx.x * blockDim.x + threadIdx.x;
    if (i < n) { g_deg[i] = 0; g_cursor[i] = 0; }
}

__global__ void count_kernel(const int* __restrict__ dst, int e) {
    int i = blockIdx.x * blockDim.x + threadIdx.x;
    if (i < e) atomicAdd(&g_deg[dst[i]], 1);
}

__global__ void scan_kernel(int n, int e) {
    __shared__ int sums[1024];
    int t = threadIdx.x;
    int chunk = (n + 1023) >> 10;
    int b = t * chunk;
    int en = min(b + chunk, n);
    int s = 0;
    for (int i = b; i < en; i++) s += g_deg[i];
    sums[t] = s;
    __syncthreads();
    for (int off = 1; off < 1024; off <<= 1) {
        int v = 0;
        if (t >= off) v = sums[t - off];
        __syncthreads();
        if (t >= off) sums[t] += v;
        __syncthreads();
    }
    int run = (t == 0) ? 0 : sums[t - 1];
    for (int i = b; i < en; i++) { g_rowptr[i] = run; run += g_deg[i]; }
    if (t == 0) g_rowptr[n] = e;
}

__global__ void scatter_kernel(const int* __restrict__ src,
                               const int* __restrict__ dst, int e) {
    int i = blockIdx.x * blockDim.x + threadIdx.x;
    if (i < e) {
        int d = dst[i];
        int pos = g_rowptr[d] + atomicAdd(&g_cursor[d], 1);
        g_srcs[pos] = src[i];
    }
}

// ---------------- layer-1 GEMM: C = feat @ W + b, [n,128]x[128,256] ----------------
__global__ __launch_bounds__(256) void sgemm_kernel(
    const float* __restrict__ A,
    const float* __restrict__ Ws, const float* __restrict__ bs,
    const float* __restrict__ Wd, const float* __restrict__ bd,
    int n)
{
    const float* B    = blockIdx.z ? Wd : Ws;
    const float* bias = blockIdx.z ? bd : bs;
    float* C          = blockIdx.z ? g_hd1 : g_hs1;

    const int rowBase = blockIdx.y * 128;
    const int colBase = blockIdx.x * 128;

    __shared__ float As[2][16][128];
    __shared__ float Bs[2][16][128];

    const int tid = threadIdx.x;
    const int tx = tid & 15;
    const int ty = tid >> 4;

    float acc[8][8];
#pragma unroll
    for (int i = 0; i < 8; i++)
#pragma unroll
        for (int j = 0; j < 8; j++) acc[i][j] = 0.f;

    const int aRow0 = tid >> 2;
    const int aK0   = (tid & 3) << 2;
    const int bK0   = tid >> 5;
    const int bCol0 = (tid & 31) << 2;

    const int gr0 = rowBase + aRow0;
    const int gr1 = rowBase + aRow0 + 64;

    float4 ra0, ra1, rb0, rb1;

    ra0 = (gr0 < n) ? *(const float4*)&A[(size_t)gr0 * F_IN + aK0] : make_float4(0, 0, 0, 0);
    ra1 = (gr1 < n) ? *(const float4*)&A[(size_t)gr1 * F_IN + aK0] : make_float4(0, 0, 0, 0);
    rb0 = *(const float4*)&B[(size_t)bK0 * HH + colBase + bCol0];
    rb1 = *(const float4*)&B[(size_t)(bK0 + 8) * HH + colBase + bCol0];

    As[0][aK0 + 0][aRow0] = ra0.x; As[0][aK0 + 1][aRow0] = ra0.y;
    As[0][aK0 + 2][aRow0] = ra0.z; As[0][aK0 + 3][aRow0] = ra0.w;
    As[0][aK0 + 0][aRow0 + 64] = ra1.x; As[0][aK0 + 1][aRow0 + 64] = ra1.y;
    As[0][aK0 + 2][aRow0 + 64] = ra1.z; As[0][aK0 + 3][aRow0 + 64] = ra1.w;
    *(float4*)&Bs[0][bK0][bCol0]     = rb0;
    *(float4*)&Bs[0][bK0 + 8][bCol0] = rb1;
    __syncthreads();

#pragma unroll
    for (int kt = 0; kt < 8; kt++) {
        const int cur = kt & 1;
        if (kt < 7) {
            const int kb = (kt + 1) * 16;
            ra0 = (gr0 < n) ? *(const float4*)&A[(size_t)gr0 * F_IN + kb + aK0] : make_float4(0, 0, 0, 0);
            ra1 = (gr1 < n) ? *(const float4*)&A[(size_t)gr1 * F_IN + kb + aK0] : make_float4(0, 0, 0, 0);
            rb0 = *(const float4*)&B[(size_t)(kb + bK0) * HH + colBase + bCol0];
            rb1 = *(const float4*)&B[(size_t)(kb + bK0 + 8) * HH + colBase + bCol0];
        }
#pragma unroll
        for (int k = 0; k < 16; k++) {
            float a[8], b[8];
            *(float4*)&a[0] = *(const float4*)&As[cur][k][ty * 8];
            *(float4*)&a[4] = *(const float4*)&As[cur][k][ty * 8 + 4];
            *(float4*)&b[0] = *(const float4*)&Bs[cur][k][tx * 8];
            *(float4*)&b[4] = *(const float4*)&Bs[cur][k][tx * 8 + 4];
#pragma unroll
            for (int i = 0; i < 8; i++)
#pragma unroll
                for (int j = 0; j < 8; j++) acc[i][j] += a[i] * b[j];
        }
        if (kt < 7) {
            const int nxt = cur ^ 1;
            As[nxt][aK0 + 0][aRow0] = ra0.x; As[nxt][aK0 + 1][aRow0] = ra0.y;
            As[nxt][aK0 + 2][aRow0] = ra0.z; As[nxt][aK0 + 3][aRow0] = ra0.w;
            As[nxt][aK0 + 0][aRow0 + 64] = ra1.x; As[nxt][aK0 + 1][aRow0 + 64] = ra1.y;
            As[nxt][aK0 + 2][aRow0 + 64] = ra1.z; As[nxt][aK0 + 3][aRow0 + 64] = ra1.w;
            *(float4*)&Bs[nxt][bK0][bCol0]     = rb0;
            *(float4*)&Bs[nxt][bK0 + 8][bCol0] = rb1;
            __syncthreads();
        }
    }

#pragma unroll
    for (int i = 0; i < 8; i++) {
        int gr = rowBase + ty * 8 + i;
        if (gr < n) {
#pragma unroll
            for (int j = 0; j < 8; j += 4) {
                int col = colBase + tx * 8 + j;
                float4 v;
                v.x = acc[i][j + 0] + bias[col + 0];
                v.y = acc[i][j + 1] + bias[col + 1];
                v.z = acc[i][j + 2] + bias[col + 2];
                v.w = acc[i][j + 3] + bias[col + 3];
                *(float4*)&C[(size_t)gr * HH + col] = v;
            }
        }
    }
}

// ---------------- layer-1 edge phase, 4-edge batched online softmax ----------------
// One warp per dst node; lane l owns dims [l*8, l*8+8); head = l/8.
// 4 edges per iteration: batched gathers (MLP=8/lane), independent scores/exps,
// single combined rescale. Epilogue fuses ELU + both layer-2 GEMVs.
__global__ __launch_bounds__(256) void edge1_kernel(
    const float* __restrict__ attn1,
    const float* __restrict__ W2s, const float* __restrict__ b2s,
    const float* __restrict__ W2d, const float* __restrict__ b2d,
    int n)
{
    const int warp = (blockIdx.x * blockDim.x + threadIdx.x) >> 5;
    const int lane = threadIdx.x & 31;
    if (warp >= n) return;

    const float4* hdp = (const float4*)&g_hd1[(size_t)warp * HH + lane * 8];
    const float4 hd0 = hdp[0], hd1 = hdp[1];
    const float4* ap = (const float4*)(attn1 + lane * 8);
    const float4 a0 = __ldg(ap), a1 = __ldg(ap + 1);

    const int beg = g_rowptr[warp];
    const int cnt = g_rowptr[warp + 1] - beg;
    const int* sp = g_srcs + beg;

    float m = __int_as_float(0xff800000);   // -inf
    float s = 0.f;
    float4 acc0 = make_float4(0, 0, 0, 0);
    float4 acc1 = make_float4(0, 0, 0, 0);

    int k = 0;
    for (; k + 4 <= cnt; k += 4) {
        int sv[4];
#pragma unroll
        for (int j = 0; j < 4; j++) sv[j] = __ldg(&sp[k + j]);

        float4 H0[4], H1[4];
#pragma unroll
        for (int j = 0; j < 4; j++) {
            const float4* hp = (const float4*)&g_hs1[(size_t)sv[j] * HH + lane * 8];
            H0[j] = __ldg(hp);
            H1[j] = __ldg(hp + 1);
        }

        float p[4];
#pragma unroll
        for (int j = 0; j < 4; j++) {
            p[j] = lrelu(H0[j].x + hd0.x) * a0.x + lrelu(H0[j].y + hd0.y) * a0.y
                 + lrelu(H0[j].z + hd0.z) * a0.z + lrelu(H0[j].w + hd0.w) * a0.w
                 + lrelu(H1[j].x + hd1.x) * a1.x + lrelu(H1[j].y + hd1.y) * a1.y
                 + lrelu(H1[j].z + hd1.z) * a1.z + lrelu(H1[j].w + hd1.w) * a1.w;
        }
#pragma unroll
        for (int j = 0; j < 4; j++) p[j] += __shfl_xor_sync(0xffffffffu, p[j], 4);
#pragma unroll
        for (int j = 0; j < 4; j++) p[j] += __shfl_xor_sync(0xffffffffu, p[j], 2);
#pragma unroll
        for (int j = 0; j < 4; j++) p[j] += __shfl_xor_sync(0xffffffffu, p[j], 1);

        const float nm = fmaxf(fmaxf(fmaxf(p[0], p[1]), fmaxf(p[2], p[3])), m);
        const float fac = __expf(m - nm);
        float w[4];
#pragma unroll
        for (int j = 0; j < 4; j++) w[j] = __expf(p[j] - nm);

        s = fmaf(s, fac, w[0] + w[1] + w[2] + w[3]);
        acc0.x = fmaf(acc0.x, fac, w[0]*H0[0].x + w[1]*H0[1].x + w[2]*H0[2].x + w[3]*H0[3].x);
        acc0.y = fmaf(acc0.y, fac, w[0]*H0[0].y + w[1]*H0[1].y + w[2]*H0[2].y + w[3]*H0[3].y);
        acc0.z = fmaf(acc0.z, fac, w[0]*H0[0].z + w[1]*H0[1].z + w[2]*H0[2].z + w[3]*H0[3].z);
        acc0.w = fmaf(acc0.w, fac, w[0]*H0[0].w + w[1]*H0[1].w + w[2]*H0[2].w + w[3]*H0[3].w);
        acc1.x = fmaf(acc1.x, fac, w[0]*H1[0].x + w[1]*H1[1].x + w[2]*H1[2].x + w[3]*H1[3].x);
        acc1.y = fmaf(acc1.y, fac, w[0]*H1[0].y + w[1]*H1[1].y + w[2]*H1[2].y + w[3]*H1[3].y);
        acc1.z = fmaf(acc1.z, fac, w[0]*H1[0].z + w[1]*H1[1].z + w[2]*H1[2].z + w[3]*H1[3].z);
        acc1.w = fmaf(acc1.w, fac, w[0]*H1[0].w + w[1]*H1[1].w + w[2]*H1[2].w + w[3]*H1[3].w);
        m = nm;
    }

    for (; k < cnt; k++) {
        const int sv = __ldg(&sp[k]);
        const float4* hp = (const float4*)&g_hs1[(size_t)sv * HH + lane * 8];
        const float4 h0 = __ldg(hp);
        const float4 h1 = __ldg(hp + 1);

        float p = lrelu(h0.x + hd0.x) * a0.x + lrelu(h0.y + hd0.y) * a0.y
                + lrelu(h0.z + hd0.z) * a0.z + lrelu(h0.w + hd0.w) * a0.w
                + lrelu(h1.x + hd1.x) * a1.x + lrelu(h1.y + hd1.y) * a1.y
                + lrelu(h1.z + hd1.z) * a1.z + lrelu(h1.w + hd1.w) * a1.w;
        p += __shfl_xor_sync(0xffffffffu, p, 4);
        p += __shfl_xor_sync(0xffffffffu, p, 2);
        p += __shfl_xor_sync(0xffffffffu, p, 1);

        const float nm  = fmaxf(m, p);
        const float fac = __expf(m - nm);
        const float w   = __expf(p - nm);
        s = fmaf(s, fac, w);
        acc0.x = fmaf(acc0.x, fac, w * h0.x);  acc0.y = fmaf(acc0.y, fac, w * h0.y);
        acc0.z = fmaf(acc0.z, fac, w * h0.z);  acc0.w = fmaf(acc0.w, fac, w * h0.w);
        acc1.x = fmaf(acc1.x, fac, w * h1.x);  acc1.y = fmaf(acc1.y, fac, w * h1.y);
        acc1.z = fmaf(acc1.z, fac, w * h1.z);  acc1.w = fmaf(acc1.w, fac, w * h1.w);
        m = nm;
    }

    const float inv = (s > 0.f) ? (1.f / s) : 0.f;
    float o[8] = { acc0.x * inv, acc0.y * inv, acc0.z * inv, acc0.w * inv,
                   acc1.x * inv, acc1.y * inv, acc1.z * inv, acc1.w * inv };

    // fused: ELU + layer-2 projections ([256] -> 2, two weight matrices)
    float s0 = 0.f, s1 = 0.f, d0 = 0.f, d1 = 0.f;
#pragma unroll
    for (int j = 0; j < 8; j++) {
        const float oj = (o[j] > 0.f) ? o[j] : expm1f(o[j]);   // ELU
        const int dix = lane * 8 + j;
        const float2 ws = __ldg((const float2*)&W2s[dix * 2]);
        const float2 wd = __ldg((const float2*)&W2d[dix * 2]);
        s0 += oj * ws.x;  s1 += oj * ws.y;
        d0 += oj * wd.x;  d1 += oj * wd.y;
    }
#pragma unroll
    for (int off = 16; off > 0; off >>= 1) {
        s0 += __shfl_xor_sync(0xffffffffu, s0, off);
        s1 += __shfl_xor_sync(0xffffffffu, s1, off);
        d0 += __shfl_xor_sync(0xffffffffu, d0, off);
        d1 += __shfl_xor_sync(0xffffffffu, d1, off);
    }
    if (lane == 0) {
        g_hs2[warp] = make_float2(s0 + __ldg(&b2s[0]), s1 + __ldg(&b2s[1]));
        g_hd2[warp] = make_float2(d0 + __ldg(&b2d[0]), d1 + __ldg(&b2d[1]));
    }
}

// ---------------- layer-2 edge phase: one thread per dst node, 4-edge batch ----------------
__global__ void edge2_kernel(const float* __restrict__ attn2,
                             float* __restrict__ out, int n)
{
    const int node = blockIdx.x * blockDim.x + threadIdx.x;
    if (node >= n) return;

    const float2 hd = g_hd2[node];
    const float ax = __ldg(&attn2[0]);
    const float ay = __ldg(&attn2[1]);

    const int beg = g_rowptr[node];
    const int cnt = g_rowptr[node + 1] - beg;
    const int* sp = g_srcs + beg;

    float m = __int_as_float(0xff800000);
    float s = 0.f, a0 = 0.f, a1 = 0.f;

    int k = 0;
    for (; k + 4 <= cnt; k += 4) {
        float2 hs[4];
#pragma unroll
        for (int j = 0; j < 4; j++) hs[j] = __ldg(&g_hs2[__ldg(&sp[k + j])]);
        float p[4];
#pragma unroll
        for (int j = 0; j < 4; j++)
            p[j] = lrelu(hs[j].x + hd.x) * ax + lrelu(hs[j].y + hd.y) * ay;

        const float nm = fmaxf(fmaxf(fmaxf(p[0], p[1]), fmaxf(p[2], p[3])), m);
        const float fac = __expf(m - nm);
        float w[4];
#pragma unroll
        for (int j = 0; j < 4; j++) w[j] = __expf(p[j] - nm);

        s  = fmaf(s,  fac, w[0] + w[1] + w[2] + w[3]);
        a0 = fmaf(a0, fac, w[0]*hs[0].x + w[1]*hs[1].x + w[2]*hs[2].x + w[3]*hs[3].x);
        a1 = fmaf(a1, fac, w[0]*hs[0].y + w[1]*hs[1].y + w[2]*hs[2].y + w[3]*hs[3].y);
        m = nm;
    }
    for (; k < cnt; k++) {
        const float2 hs = __ldg(&g_hs2[__ldg(&sp[k])]);
        const float p = lrelu(hs.x + hd.x) * ax + lrelu(hs.y + hd.y) * ay;
        const float nm  = fmaxf(m, p);
        const float fac = __expf(m - nm);
        const float w   = __expf(p - nm);
        s  = fmaf(s,  fac, w);
        a0 = fmaf(a0, fac, w * hs.x);
        a1 = fmaf(a1, fac, w * hs.y);
        m = nm;
    }
    const float inv = (s > 0.f) ? (1.f / s) : 0.f;
    out[(size_t)node * 2 + 0] = a0 * inv;
    out[(size_t)node * 2 + 1] = a1 * inv;
}

// ---------------- launch ----------------
extern "C" void kernel_launch(void* const* d_in, const int* in_sizes, int n_in,
                              void* d_out, int out_size)
{
    const float* feat  = (const float*)d_in[0];
    const int*   src   = (const int*)  d_in[1];
    const int*   dst   = (const int*)  d_in[2];
    const float* W1s   = (const float*)d_in[3];
    const float* b1s   = (const float*)d_in[4];
    const float* W1d   = (const float*)d_in[5];
    const float* b1d   = (const float*)d_in[6];
    const float* attn1 = (const float*)d_in[7];
    const float* W2s   = (const float*)d_in[8];
    const float* b2s   = (const float*)d_in[9];
    const float* W2d   = (const float*)d_in[10];
    const float* b2d   = (const float*)d_in[11];
    const float* attn2 = (const float*)d_in[12];

    const int n = in_sizes[0] / F_IN;
    const int e = in_sizes[1];

    // CSR build (adjacency holds src node ids directly)
    init_kernel<<<(n + 255) / 256, 256>>>(n);
    count_kernel<<<(e + 255) / 256, 256>>>(dst, e);
    scan_kernel<<<1, 1024>>>(n, e);
    scatter_kernel<<<(e + 255) / 256, 256>>>(src, dst, e);

    // layer-1 projections (hs1, hd1)
    dim3 g1(2, (n + 127) / 128, 2);
    sgemm_kernel<<<g1, 256>>>(feat, W1s, b1s, W1d, b1d, n);

    // layer-1 attention + aggregation + ELU + layer-2 GEMV (fused)
    edge1_kernel<<<(n + 7) / 8, 256>>>(attn1, W2s, b2s, W2d, b2d, n);

    // layer-2 attention + aggregation -> output [n,2]
    edge2_kernel<<<(n + 255) / 256, 256>>>(attn2, (float*)d_out, n);
}

// round 5
// speedup vs baseline: 1.5934x; 1.4208x over previous
#include <cuda_runtime.h>
#include <math.h>

#define N_MAX 50000
#define E_MAX 800000
#define F_IN 128
#define HH 256           // HEADS*HID = 4*64
#define NEG_SLOPE 0.2f

// ---------------- scratch (static device, no allocation) ----------------
__device__ __align__(16) float g_hs1[(size_t)N_MAX * HH];
__device__ __align__(16) float g_hd1[(size_t)N_MAX * HH];
__device__ __align__(16) float2 g_hs2[N_MAX];
__device__ __align__(16) float2 g_hd2[N_MAX];
__device__ int g_deg[N_MAX];
__device__ int g_cursor[N_MAX];
__device__ int g_rowptr[N_MAX + 1];
__device__ int g_srcs[E_MAX];     // src node id, grouped by dst (CSR adjacency)

__device__ __forceinline__ float lrelu(float x) {
    return x > 0.f ? x : NEG_SLOPE * x;
}

// packed f32x2 helpers (Blackwell 2xFP32 pipe; ptxas never auto-fuses these)
__device__ __forceinline__ unsigned long long pack2(float lo, float hi) {
    unsigned long long r;
    asm("mov.b64 %0, {%1, %2};" : "=l"(r) : "f"(lo), "f"(hi));
    return r;
}
__device__ __forceinline__ unsigned long long pack_dup(float v) {
    unsigned long long r;
    asm("mov.b64 %0, {%1, %1};" : "=l"(r) : "f"(v));
    return r;
}
__device__ __forceinline__ void fma2(unsigned long long& acc,
                                     unsigned long long a, unsigned long long b) {
    asm("fma.rn.f32x2 %0, %1, %2, %0;" : "+l"(acc) : "l"(a), "l"(b));
}
__device__ __forceinline__ void unpack2(unsigned long long p, float& lo, float& hi) {
    asm("mov.b64 {%0, %1}, %2;" : "=f"(lo), "=f"(hi) : "l"(p));
}

// ---------------- CSR build ----------------
__global__ void init_kernel(int n) {
    int i = blockIdx.x * blockDim.x + threadIdx.x;
    if (i < n) { g_deg[i] = 0; g_cursor[i] = 0; }
}

__global__ void count_kernel(const int* __restrict__ dst, int e) {
    int i = blockIdx.x * blockDim.x + threadIdx.x;
    if (i < e) atomicAdd(&g_deg[dst[i]], 1);
}

__global__ void scan_kernel(int n, int e) {
    __shared__ int sums[1024];
    int t = threadIdx.x;
    int chunk = (n + 1023) >> 10;
    int b = t * chunk;
    int en = min(b + chunk, n);
    int s = 0;
    for (int i = b; i < en; i++) s += g_deg[i];
    sums[t] = s;
    __syncthreads();
    for (int off = 1; off < 1024; off <<= 1) {
        int v = 0;
        if (t >= off) v = sums[t - off];
        __syncthreads();
        if (t >= off) sums[t] += v;
        __syncthreads();
    }
    int run = (t == 0) ? 0 : sums[t - 1];
    for (int i = b; i < en; i++) { g_rowptr[i] = run; run += g_deg[i]; }
    if (t == 0) g_rowptr[n] = e;
}

__global__ void scatter_kernel(const int* __restrict__ src,
                               const int* __restrict__ dst, int e) {
    int i = blockIdx.x * blockDim.x + threadIdx.x;
    if (i < e) {
        int d = dst[i];
        int pos = g_rowptr[d] + atomicAdd(&g_cursor[d], 1);
        g_srcs[pos] = src[i];
    }
}

// ---------------- layer-1 GEMM: C = feat @ W + b, [n,128]x[128,256] ----------------
// BM=128, BN=128, BK=16, 256 threads, 8x8 microtile held as 8x4 packed f32x2,
// inner product issued on the 2xFP32 pipe via fma.rn.f32x2.
__global__ __launch_bounds__(256) void sgemm_kernel(
    const float* __restrict__ A,
    const float* __restrict__ Ws, const float* __restrict__ bs,
    const float* __restrict__ Wd, const float* __restrict__ bd,
    int n)
{
    const float* B    = blockIdx.z ? Wd : Ws;
    const float* bias = blockIdx.z ? bd : bs;
    float* C          = blockIdx.z ? g_hd1 : g_hs1;

    const int rowBase = blockIdx.y * 128;
    const int colBase = blockIdx.x * 128;

    __shared__ float As[2][16][128];
    __shared__ float Bs[2][16][128];

    const int tid = threadIdx.x;
    const int tx = tid & 15;
    const int ty = tid >> 4;

    unsigned long long accp[8][4];   // acc[i][2j], acc[i][2j+1] packed
#pragma unroll
    for (int i = 0; i < 8; i++)
#pragma unroll
        for (int j = 0; j < 4; j++) accp[i][j] = 0ull;

    const int aRow0 = tid >> 2;
    const int aK0   = (tid & 3) << 2;
    const int bK0   = tid >> 5;
    const int bCol0 = (tid & 31) << 2;

    const int gr0 = rowBase + aRow0;
    const int gr1 = rowBase + aRow0 + 64;

    float4 ra0, ra1, rb0, rb1;

    ra0 = (gr0 < n) ? *(const float4*)&A[(size_t)gr0 * F_IN + aK0] : make_float4(0, 0, 0, 0);
    ra1 = (gr1 < n) ? *(const float4*)&A[(size_t)gr1 * F_IN + aK0] : make_float4(0, 0, 0, 0);
    rb0 = *(const float4*)&B[(size_t)bK0 * HH + colBase + bCol0];
    rb1 = *(const float4*)&B[(size_t)(bK0 + 8) * HH + colBase + bCol0];

    As[0][aK0 + 0][aRow0] = ra0.x; As[0][aK0 + 1][aRow0] = ra0.y;
    As[0][aK0 + 2][aRow0] = ra0.z; As[0][aK0 + 3][aRow0] = ra0.w;
    As[0][aK0 + 0][aRow0 + 64] = ra1.x; As[0][aK0 + 1][aRow0 + 64] = ra1.y;
    As[0][aK0 + 2][aRow0 + 64] = ra1.z; As[0][aK0 + 3][aRow0 + 64] = ra1.w;
    *(float4*)&Bs[0][bK0][bCol0]     = rb0;
    *(float4*)&Bs[0][bK0 + 8][bCol0] = rb1;
    __syncthreads();

#pragma unroll
    for (int kt = 0; kt < 8; kt++) {
        const int cur = kt & 1;
        if (kt < 7) {
            const int kb = (kt + 1) * 16;
            ra0 = (gr0 < n) ? *(const float4*)&A[(size_t)gr0 * F_IN + kb + aK0] : make_float4(0, 0, 0, 0);
            ra1 = (gr1 < n) ? *(const float4*)&A[(size_t)gr1 * F_IN + kb + aK0] : make_float4(0, 0, 0, 0);
            rb0 = *(const float4*)&B[(size_t)(kb + bK0) * HH + colBase + bCol0];
            rb1 = *(const float4*)&B[(size_t)(kb + bK0 + 8) * HH + colBase + bCol0];
        }
#pragma unroll
        for (int k = 0; k < 16; k++) {
            float a[8], b[8];
            *(float4*)&a[0] = *(const float4*)&As[cur][k][ty * 8];
            *(float4*)&a[4] = *(const float4*)&As[cur][k][ty * 8 + 4];
            *(float4*)&b[0] = *(const float4*)&Bs[cur][k][tx * 8];
            *(float4*)&b[4] = *(const float4*)&Bs[cur][k][tx * 8 + 4];

            unsigned long long bp[4];
#pragma unroll
            for (int j = 0; j < 4; j++) bp[j] = pack2(b[2 * j], b[2 * j + 1]);
#pragma unroll
            for (int i = 0; i < 8; i++) {
                const unsigned long long ap = pack_dup(a[i]);
#pragma unroll
                for (int j = 0; j < 4; j++) fma2(accp[i][j], ap, bp[j]);
            }
        }
        if (kt < 7) {
            const int nxt = cur ^ 1;
            As[nxt][aK0 + 0][aRow0] = ra0.x; As[nxt][aK0 + 1][aRow0] = ra0.y;
            As[nxt][aK0 + 2][aRow0] = ra0.z; As[nxt][aK0 + 3][aRow0] = ra0.w;
            As[nxt][aK0 + 0][aRow0 + 64] = ra1.x; As[nxt][aK0 + 1][aRow0 + 64] = ra1.y;
            As[nxt][aK0 + 2][aRow0 + 64] = ra1.z; As[nxt][aK0 + 3][aRow0 + 64] = ra1.w;
            *(float4*)&Bs[nxt][bK0][bCol0]     = rb0;
            *(float4*)&Bs[nxt][bK0 + 8][bCol0] = rb1;
            __syncthreads();
        }
    }

#pragma unroll
    for (int i = 0; i < 8; i++) {
        int gr = rowBase + ty * 8 + i;
        if (gr < n) {
#pragma unroll
            for (int j = 0; j < 2; j++) {
                int col = colBase + tx * 8 + j * 4;
                float4 v;
                unpack2(accp[i][2 * j + 0], v.x, v.y);
                unpack2(accp[i][2 * j + 1], v.z, v.w);
                v.x += bias[col + 0];
                v.y += bias[col + 1];
                v.z += bias[col + 2];
                v.w += bias[col + 3];
                *(float4*)&C[(size_t)gr * HH + col] = v;
            }
        }
    }
}

// ---------------- layer-1 edge phase, 4-edge batched online softmax ----------------
__global__ __launch_bounds__(256) void edge1_kernel(
    const float* __restrict__ attn1,
    const float* __restrict__ W2s, const float* __restrict__ b2s,
    const float* __restrict__ W2d, const float* __restrict__ b2d,
    int n)
{
    const int warp = (blockIdx.x * blockDim.x + threadIdx.x) >> 5;
    const int lane = threadIdx.x & 31;
    if (warp >= n) return;

    const float4* hdp = (const float4*)&g_hd1[(size_t)warp * HH + lane * 8];
    const float4 hd0 = hdp[0], hd1 = hdp[1];
    const float4* ap = (const float4*)(attn1 + lane * 8);
    const float4 a0 = __ldg(ap), a1 = __ldg(ap + 1);

    const int beg = g_rowptr[warp];
    const int cnt = g_rowptr[warp + 1] - beg;
    const int* sp = g_srcs + beg;

    float m = __int_as_float(0xff800000);   // -inf
    float s = 0.f;
    float4 acc0 = make_float4(0, 0, 0, 0);
    float4 acc1 = make_float4(0, 0, 0, 0);

    int k = 0;
    for (; k + 4 <= cnt; k += 4) {
        int sv[4];
#pragma unroll
        for (int j = 0; j < 4; j++) sv[j] = __ldg(&sp[k + j]);

        float4 H0[4], H1[4];
#pragma unroll
        for (int j = 0; j < 4; j++) {
            const float4* hp = (const float4*)&g_hs1[(size_t)sv[j] * HH + lane * 8];
            H0[j] = __ldg(hp);
            H1[j] = __ldg(hp + 1);
        }

        float p[4];
#pragma unroll
        for (int j = 0; j < 4; j++) {
            p[j] = lrelu(H0[j].x + hd0.x) * a0.x + lrelu(H0[j].y + hd0.y) * a0.y
                 + lrelu(H0[j].z + hd0.z) * a0.z + lrelu(H0[j].w + hd0.w) * a0.w
                 + lrelu(H1[j].x + hd1.x) * a1.x + lrelu(H1[j].y + hd1.y) * a1.y
                 + lrelu(H1[j].z + hd1.z) * a1.z + lrelu(H1[j].w + hd1.w) * a1.w;
        }
#pragma unroll
        for (int j = 0; j < 4; j++) p[j] += __shfl_xor_sync(0xffffffffu, p[j], 4);
#pragma unroll
        for (int j = 0; j < 4; j++) p[j] += __shfl_xor_sync(0xffffffffu, p[j], 2);
#pragma unroll
        for (int j = 0; j < 4; j++) p[j] += __shfl_xor_sync(0xffffffffu, p[j], 1);

        const float nm = fmaxf(fmaxf(fmaxf(p[0], p[1]), fmaxf(p[2], p[3])), m);
        const float fac = __expf(m - nm);
        float w[4];
#pragma unroll
        for (int j = 0; j < 4; j++) w[j] = __expf(p[j] - nm);

        s = fmaf(s, fac, w[0] + w[1] + w[2] + w[3]);
        acc0.x = fmaf(acc0.x, fac, w[0]*H0[0].x + w[1]*H0[1].x + w[2]*H0[2].x + w[3]*H0[3].x);
        acc0.y = fmaf(acc0.y, fac, w[0]*H0[0].y + w[1]*H0[1].y + w[2]*H0[2].y + w[3]*H0[3].y);
        acc0.z = fmaf(acc0.z, fac, w[0]*H0[0].z + w[1]*H0[1].z + w[2]*H0[2].z + w[3]*H0[3].z);
        acc0.w = fmaf(acc0.w, fac, w[0]*H0[0].w + w[1]*H0[1].w + w[2]*H0[2].w + w[3]*H0[3].w);
        acc1.x = fmaf(acc1.x, fac, w[0]*H1[0].x + w[1]*H1[1].x + w[2]*H1[2].x + w[3]*H1[3].x);
        acc1.y = fmaf(acc1.y, fac, w[0]*H1[0].y + w[1]*H1[1].y + w[2]*H1[2].y + w[3]*H1[3].y);
        acc1.z = fmaf(acc1.z, fac, w[0]*H1[0].z + w[1]*H1[1].z + w[2]*H1[2].z + w[3]*H1[3].z);
        acc1.w = fmaf(acc1.w, fac, w[0]*H1[0].w + w[1]*H1[1].w + w[2]*H1[2].w + w[3]*H1[3].w);
        m = nm;
    }

    for (; k < cnt; k++) {
        const int sv = __ldg(&sp[k]);
        const float4* hp = (const float4*)&g_hs1[(size_t)sv * HH + lane * 8];
        const float4 h0 = __ldg(hp);
        const float4 h1 = __ldg(hp + 1);

        float p = lrelu(h0.x + hd0.x) * a0.x + lrelu(h0.y + hd0.y) * a0.y
                + lrelu(h0.z + hd0.z) * a0.z + lrelu(h0.w + hd0.w) * a0.w
                + lrelu(h1.x + hd1.x) * a1.x + lrelu(h1.y + hd1.y) * a1.y
                + lrelu(h1.z + hd1.z) * a1.z + lrelu(h1.w + hd1.w) * a1.w;
        p += __shfl_xor_sync(0xffffffffu, p, 4);
        p += __shfl_xor_sync(0xffffffffu, p, 2);
        p += __shfl_xor_sync(0xffffffffu, p, 1);

        const float nm  = fmaxf(m, p);
        const float fac = __expf(m - nm);
        const float w   = __expf(p - nm);
        s = fmaf(s, fac, w);
        acc0.x = fmaf(acc0.x, fac, w * h0.x);  acc0.y = fmaf(acc0.y, fac, w * h0.y);
        acc0.z = fmaf(acc0.z, fac, w * h0.z);  acc0.w = fmaf(acc0.w, fac, w * h0.w);
        acc1.x = fmaf(acc1.x, fac, w * h1.x);  acc1.y = fmaf(acc1.y, fac, w * h1.y);
        acc1.z = fmaf(acc1.z, fac, w * h1.z);  acc1.w = fmaf(acc1.w, fac, w * h1.w);
        m = nm;
    }

    const float inv = (s > 0.f) ? (1.f / s) : 0.f;
    float o[8] = { acc0.x * inv, acc0.y * inv, acc0.z * inv, acc0.w * inv,
                   acc1.x * inv, acc1.y * inv, acc1.z * inv, acc1.w * inv };

    // fused: ELU + layer-2 projections ([256] -> 2, two weight matrices)
    float s0 = 0.f, s1 = 0.f, d0 = 0.f, d1 = 0.f;
#pragma unroll
    for (int j = 0; j < 8; j++) {
        const float oj = (o[j] > 0.f) ? o[j] : expm1f(o[j]);   // ELU
        const int dix = lane * 8 + j;
        const float2 ws = __ldg((const float2*)&W2s[dix * 2]);
        const float2 wd = __ldg((const float2*)&W2d[dix * 2]);
        s0 += oj * ws.x;  s1 += oj * ws.y;
        d0 += oj * wd.x;  d1 += oj * wd.y;
    }
#pragma unroll
    for (int off = 16; off > 0; off >>= 1) {
        s0 += __shfl_xor_sync(0xffffffffu, s0, off);
        s1 += __shfl_xor_sync(0xffffffffu, s1, off);
        d0 += __shfl_xor_sync(0xffffffffu, d0, off);
        d1 += __shfl_xor_sync(0xffffffffu, d1, off);
    }
    if (lane == 0) {
        g_hs2[warp] = make_float2(s0 + __ldg(&b2s[0]), s1 + __ldg(&b2s[1]));
        g_hd2[warp] = make_float2(d0 + __ldg(&b2d[0]), d1 + __ldg(&b2d[1]));
    }
}

// ---------------- layer-2 edge phase: one thread per dst node, 4-edge batch ----------------
__global__ void edge2_kernel(const float* __restrict__ attn2,
                             float* __restrict__ out, int n)
{
    const int node = blockIdx.x * blockDim.x + threadIdx.x;
    if (node >= n) return;

    const float2 hd = g_hd2[node];
    const float ax = __ldg(&attn2[0]);
    const float ay = __ldg(&attn2[1]);

    const int beg = g_rowptr[node];
    const int cnt = g_rowptr[node + 1] - beg;
    const int* sp = g_srcs + beg;

    float m = __int_as_float(0xff800000);
    float s = 0.f, a0 = 0.f, a1 = 0.f;

    int k = 0;
    for (; k + 4 <= cnt; k += 4) {
        float2 hs[4];
#pragma unroll
        for (int j = 0; j < 4; j++) hs[j] = __ldg(&g_hs2[__ldg(&sp[k + j])]);
        float p[4];
#pragma unroll
        for (int j = 0; j < 4; j++)
            p[j] = lrelu(hs[j].x + hd.x) * ax + lrelu(hs[j].y + hd.y) * ay;

        const float nm = fmaxf(fmaxf(fmaxf(p[0], p[1]), fmaxf(p[2], p[3])), m);
        const float fac = __expf(m - nm);
        float w[4];
#pragma unroll
        for (int j = 0; j < 4; j++) w[j] = __expf(p[j] - nm);

        s  = fmaf(s,  fac, w[0] + w[1] + w[2] + w[3]);
        a0 = fmaf(a0, fac, w[0]*hs[0].x + w[1]*hs[1].x + w[2]*hs[2].x + w[3]*hs[3].x);
        a1 = fmaf(a1, fac, w[0]*hs[0].y + w[1]*hs[1].y + w[2]*hs[2].y + w[3]*hs[3].y);
        m = nm;
    }
    for (; k < cnt; k++) {
        const float2 hs = __ldg(&g_hs2[__ldg(&sp[k])]);
        const float p = lrelu(hs.x + hd.x) * ax + lrelu(hs.y + hd.y) * ay;
        const float nm  = fmaxf(m, p);
        const float fac = __expf(m - nm);
        const float w   = __expf(p - nm);
        s  = fmaf(s,  fac, w);
        a0 = fmaf(a0, fac, w * hs.x);
        a1 = fmaf(a1, fac, w * hs.y);
        m = nm;
    }
    const float inv = (s > 0.f) ? (1.f / s) : 0.f;
    out[(size_t)node * 2 + 0] = a0 * inv;
    out[(size_t)node * 2 + 1] = a1 * inv;
}

// ---------------- launch ----------------
extern "C" void kernel_launch(void* const* d_in, const int* in_sizes, int n_in,
                              void* d_out, int out_size)
{
    const float* feat  = (const float*)d_in[0];
    const int*   src   = (const int*)  d_in[1];
    const int*   dst   = (const int*)  d_in[2];
    const float* W1s   = (const float*)d_in[3];
    const float* b1s   = (const float*)d_in[4];
    const float* W1d   = (const float*)d_in[5];
    const float* b1d   = (const float*)d_in[6];
    const float* attn1 = (const float*)d_in[7];
    const float* W2s   = (const float*)d_in[8];
    const float* b2s   = (const float*)d_in[9];
    const float* W2d   = (const float*)d_in[10];
    const float* b2d   = (const float*)d_in[11];
    const float* attn2 = (const float*)d_in[12];

    const int n = in_sizes[0] / F_IN;
    const int e = in_sizes[1];

    // CSR build + projections. sgemm placed as the 4th launch so the ncu
    // single-kernel capture window lands on it (diagnostic for next round).
    init_kernel<<<(n + 255) / 256, 256>>>(n);
    count_kernel<<<(e + 255) / 256, 256>>>(dst, e);
    scan_kernel<<<1, 1024>>>(n, e);

    dim3 g1(2, (n + 127) / 128, 2);
    sgemm_kernel<<<g1, 256>>>(feat, W1s, b1s, W1d, b1d, n);

    scatter_kernel<<<(e + 255) / 256, 256>>>(src, dst, e);

    // layer-1 attention + aggregation + ELU + layer-2 GEMV (fused)
    edge1_kernel<<<(n + 7) / 8, 256>>>(attn1, W2s, b2s, W2d, b2d, n);

    // layer-2 attention + aggregation -> output [n,2]
    edge2_kernel<<<(n + 255) / 256, 256>>>(attn2, (float*)d_out, n);
}

// round 6
// speedup vs baseline: 1.7614x; 1.1054x over previous
#include <cuda_runtime.h>
#include <math.h>

#define N_MAX 50000
#define E_MAX 800000
#define F_IN 128
#define HH 256           // HEADS*HID = 4*64
#define NEG_SLOPE 0.2f

// ---------------- scratch (static device, no allocation) ----------------
__device__ __align__(16) float g_hs1[(size_t)N_MAX * HH];
__device__ __align__(16) float g_hd1[(size_t)N_MAX * HH];
__device__ __align__(16) float2 g_hs2[N_MAX];
__device__ __align__(16) float2 g_hd2[N_MAX];
__device__ int g_deg[N_MAX];
__device__ int g_cursor[N_MAX];
__device__ int g_rowptr[N_MAX + 1];
__device__ int g_srcs[E_MAX];     // src node id, grouped by dst (CSR adjacency)

__device__ __forceinline__ float lrelu(float x) {
    return x > 0.f ? x : NEG_SLOPE * x;
}

// packed f32x2 helpers (Blackwell 2xFP32 pipe; ptxas never auto-fuses these)
__device__ __forceinline__ unsigned long long pack2(float lo, float hi) {
    unsigned long long r;
    asm("mov.b64 %0, {%1, %2};" : "=l"(r) : "f"(lo), "f"(hi));
    return r;
}
__device__ __forceinline__ unsigned long long pack_dup(float v) {
    unsigned long long r;
    asm("mov.b64 %0, {%1, %1};" : "=l"(r) : "f"(v));
    return r;
}
__device__ __forceinline__ void fma2(unsigned long long& acc,
                                     unsigned long long a, unsigned long long b) {
    asm("fma.rn.f32x2 %0, %1, %2, %0;" : "+l"(acc) : "l"(a), "l"(b));
}
__device__ __forceinline__ void unpack2(unsigned long long p, float& lo, float& hi) {
    asm("mov.b64 {%0, %1}, %2;" : "=f"(lo), "=f"(hi) : "l"(p));
}

// cp.async helpers
__device__ __forceinline__ void cp16(unsigned dst_smem, const void* src) {
    asm volatile("cp.async.cg.shared.global [%0], [%1], 16;" :: "r"(dst_smem), "l"(src));
}
__device__ __forceinline__ void cp_commit() {
    asm volatile("cp.async.commit_group;");
}
__device__ __forceinline__ void cp_wait0() {
    asm volatile("cp.async.wait_group 0;");
}

// ---------------- CSR build ----------------
__global__ void init_kernel(int n) {
    int i = blockIdx.x * blockDim.x + threadIdx.x;
    if (i < n) { g_deg[i] = 0; g_cursor[i] = 0; }
}

__global__ void count_kernel(const int* __restrict__ dst, int e) {
    int i = blockIdx.x * blockDim.x + threadIdx.x;
    if (i < e) atomicAdd(&g_deg[dst[i]], 1);
}

__global__ void scan_kernel(int n, int e) {
    __shared__ int sums[1024];
    int t = threadIdx.x;
    int chunk = (n + 1023) >> 10;
    int b = t * chunk;
    int en = min(b + chunk, n);
    int s = 0;
    for (int i = b; i < en; i++) s += g_deg[i];
    sums[t] = s;
    __syncthreads();
    for (int off = 1; off < 1024; off <<= 1) {
        int v = 0;
        if (t >= off) v = sums[t - off];
        __syncthreads();
        if (t >= off) sums[t] += v;
        __syncthreads();
    }
    int run = (t == 0) ? 0 : sums[t - 1];
    for (int i = b; i < en; i++) { g_rowptr[i] = run; run += g_deg[i]; }
    if (t == 0) g_rowptr[n] = e;
}

__global__ void scatter_kernel(const int* __restrict__ src,
                               const int* __restrict__ dst, int e) {
    int i = blockIdx.x * blockDim.x + threadIdx.x;
    if (i < e) {
        int d = dst[i];
        int pos = g_rowptr[d] + atomicAdd(&g_cursor[d], 1);
        g_srcs[pos] = src[i];
    }
}

// ---------------- layer-1 GEMM: C = feat @ W + b, [n,128]x[128,256] ----------------
// BM=128, BN=128, BK=16, 256 threads, 8x8 microtile on the f32x2 pipe.
// B tiles via cp.async into conflict-free split arrays (even/odd quads);
// A tile register-staged + transposed store. 2 CTAs/SM.
__global__ __launch_bounds__(256, 2) void sgemm_kernel(
    const float* __restrict__ A,
    const float* __restrict__ Ws, const float* __restrict__ bs,
    const float* __restrict__ Wd, const float* __restrict__ bd,
    int n)
{
    const float* B    = blockIdx.z ? Wd : Ws;
    const float* bias = blockIdx.z ? bd : bs;
    float* C          = blockIdx.z ? g_hd1 : g_hs1;

    const int rowBase = blockIdx.y * 128;
    const int colBase = blockIdx.x * 128;

    __shared__ float As [2][16][128];
    __shared__ float BsA[2][16][64];   // cols with even quad index
    __shared__ float BsB[2][16][64];   // cols with odd quad index

    const int tid = threadIdx.x;
    const int tx = tid & 15;
    const int ty = tid >> 4;

    unsigned long long accp[8][4];
#pragma unroll
    for (int i = 0; i < 8; i++)
#pragma unroll
        for (int j = 0; j < 4; j++) accp[i][j] = 0ull;

    // A-tile staging (transposed store into As[k][row])
    const int aRow0 = tid >> 2;            // 0..63
    const int aK0   = (tid & 3) << 2;      // 0,4,8,12
    const int gr0 = rowBase + aRow0;
    const int gr1 = rowBase + aRow0 + 64;

    // B-tile cp.async: thread covers quad q at k rows bK0 and bK0+8
    const int bK0 = tid >> 5;              // 0..7
    const int q   = tid & 31;              // quad index 0..31
    float* bdst = (q & 1) ? &BsB[0][0][0] : &BsA[0][0][0];
    const int bOff = (q >> 1) * 4;         // position within 64-wide row
    const unsigned bDst0 = (unsigned)__cvta_generic_to_shared(bdst + (size_t)bK0 * 64 + bOff);
    const unsigned bStageStride = 16 * 64 * 4;    // bytes between stages
    const float* bSrcBase = &B[(size_t)bK0 * HH + colBase + q * 4];

    float4 ra0, ra1;

    // ---- prologue: tile 0 ----
    ra0 = (gr0 < n) ? *(const float4*)&A[(size_t)gr0 * F_IN + aK0] : make_float4(0, 0, 0, 0);
    ra1 = (gr1 < n) ? *(const float4*)&A[(size_t)gr1 * F_IN + aK0] : make_float4(0, 0, 0, 0);
    cp16(bDst0,                 bSrcBase);
    cp16(bDst0 + 8 * 64 * 4,    bSrcBase + 8 * HH);
    cp_commit();

    As[0][aK0 + 0][aRow0] = ra0.x; As[0][aK0 + 1][aRow0] = ra0.y;
    As[0][aK0 + 2][aRow0] = ra0.z; As[0][aK0 + 3][aRow0] = ra0.w;
    As[0][aK0 + 0][aRow0 + 64] = ra1.x; As[0][aK0 + 1][aRow0 + 64] = ra1.y;
    As[0][aK0 + 2][aRow0 + 64] = ra1.z; As[0][aK0 + 3][aRow0 + 64] = ra1.w;
    cp_wait0();
    __syncthreads();

#pragma unroll
    for (int kt = 0; kt < 8; kt++) {
        const int cur = kt & 1;
        const int nxt = cur ^ 1;
        if (kt < 7) {
            const int kb = (kt + 1) * 16;
            ra0 = (gr0 < n) ? *(const float4*)&A[(size_t)gr0 * F_IN + kb + aK0] : make_float4(0, 0, 0, 0);
            ra1 = (gr1 < n) ? *(const float4*)&A[(size_t)gr1 * F_IN + kb + aK0] : make_float4(0, 0, 0, 0);
            const unsigned d = bDst0 + nxt * bStageStride;
            cp16(d,              bSrcBase + (size_t)kb * HH);
            cp16(d + 8 * 64 * 4, bSrcBase + (size_t)(kb + 8) * HH);
            cp_commit();
        }
#pragma unroll
        for (int k = 0; k < 16; k++) {
            float a[8], b[8];
            *(float4*)&a[0] = *(const float4*)&As[cur][k][ty * 8];
            *(float4*)&a[4] = *(const float4*)&As[cur][k][ty * 8 + 4];
            *(float4*)&b[0] = *(const float4*)&BsA[cur][k][tx * 4];
            *(float4*)&b[4] = *(const float4*)&BsB[cur][k][tx * 4];

            unsigned long long bp[4];
#pragma unroll
            for (int j = 0; j < 4; j++) bp[j] = pack2(b[2 * j], b[2 * j + 1]);
#pragma unroll
            for (int i = 0; i < 8; i++) {
                const unsigned long long ap = pack_dup(a[i]);
#pragma unroll
                for (int j = 0; j < 4; j++) fma2(accp[i][j], ap, bp[j]);
            }
        }
        if (kt < 7) {
            As[nxt][aK0 + 0][aRow0] = ra0.x; As[nxt][aK0 + 1][aRow0] = ra0.y;
            As[nxt][aK0 + 2][aRow0] = ra0.z; As[nxt][aK0 + 3][aRow0] = ra0.w;
            As[nxt][aK0 + 0][aRow0 + 64] = ra1.x; As[nxt][aK0 + 1][aRow0 + 64] = ra1.y;
            As[nxt][aK0 + 2][aRow0 + 64] = ra1.z; As[nxt][aK0 + 3][aRow0 + 64] = ra1.w;
            cp_wait0();
            __syncthreads();
        }
    }

    // epilogue: b[0..3]=cols tx*8..+3 (even quad), b[4..7]=tx*8+4..+7 (odd quad)
#pragma unroll
    for (int i = 0; i < 8; i++) {
        int gr = rowBase + ty * 8 + i;
        if (gr < n) {
#pragma unroll
            for (int j = 0; j < 2; j++) {
                int col = colBase + tx * 8 + j * 4;
                float4 v;
                unpack2(accp[i][2 * j + 0], v.x, v.y);
                unpack2(accp[i][2 * j + 1], v.z, v.w);
                v.x += bias[col + 0];
                v.y += bias[col + 1];
                v.z += bias[col + 2];
                v.w += bias[col + 3];
                *(float4*)&C[(size_t)gr * HH + col] = v;
            }
        }
    }
}

// ---------------- layer-1 edge phase, 4-edge batched online softmax ----------------
__global__ __launch_bounds__(256) void edge1_kernel(
    const float* __restrict__ attn1,
    const float* __restrict__ W2s, const float* __restrict__ b2s,
    const float* __restrict__ W2d, const float* __restrict__ b2d,
    int n)
{
    const int warp = (blockIdx.x * blockDim.x + threadIdx.x) >> 5;
    const int lane = threadIdx.x & 31;
    if (warp >= n) return;

    const float4* hdp = (const float4*)&g_hd1[(size_t)warp * HH + lane * 8];
    const float4 hd0 = hdp[0], hd1 = hdp[1];
    const float4* ap = (const float4*)(attn1 + lane * 8);
    const float4 a0 = __ldg(ap), a1 = __ldg(ap + 1);

    const int beg = g_rowptr[warp];
    const int cnt = g_rowptr[warp + 1] - beg;
    const int* sp = g_srcs + beg;

    float m = __int_as_float(0xff800000);   // -inf
    float s = 0.f;
    float4 acc0 = make_float4(0, 0, 0, 0);
    float4 acc1 = make_float4(0, 0, 0, 0);

    int k = 0;
    for (; k + 4 <= cnt; k += 4) {
        int sv[4];
#pragma unroll
        for (int j = 0; j < 4; j++) sv[j] = __ldg(&sp[k + j]);

        float4 H0[4], H1[4];
#pragma unroll
        for (int j = 0; j < 4; j++) {
            const float4* hp = (const float4*)&g_hs1[(size_t)sv[j] * HH + lane * 8];
            H0[j] = __ldg(hp);
            H1[j] = __ldg(hp + 1);
        }

        float p[4];
#pragma unroll
        for (int j = 0; j < 4; j++) {
            p[j] = lrelu(H0[j].x + hd0.x) * a0.x + lrelu(H0[j].y + hd0.y) * a0.y
                 + lrelu(H0[j].z + hd0.z) * a0.z + lrelu(H0[j].w + hd0.w) * a0.w
                 + lrelu(H1[j].x + hd1.x) * a1.x + lrelu(H1[j].y + hd1.y) * a1.y
                 + lrelu(H1[j].z + hd1.z) * a1.z + lrelu(H1[j].w + hd1.w) * a1.w;
        }
#pragma unroll
        for (int j = 0; j < 4; j++) p[j] += __shfl_xor_sync(0xffffffffu, p[j], 4);
#pragma unroll
        for (int j = 0; j < 4; j++) p[j] += __shfl_xor_sync(0xffffffffu, p[j], 2);
#pragma unroll
        for (int j = 0; j < 4; j++) p[j] += __shfl_xor_sync(0xffffffffu, p[j], 1);

        const float nm = fmaxf(fmaxf(fmaxf(p[0], p[1]), fmaxf(p[2], p[3])), m);
        const float fac = __expf(m - nm);
        float w[4];
#pragma unroll
        for (int j = 0; j < 4; j++) w[j] = __expf(p[j] - nm);

        s = fmaf(s, fac, w[0] + w[1] + w[2] + w[3]);
        acc0.x = fmaf(acc0.x, fac, w[0]*H0[0].x + w[1]*H0[1].x + w[2]*H0[2].x + w[3]*H0[3].x);
        acc0.y = fmaf(acc0.y, fac, w[0]*H0[0].y + w[1]*H0[1].y + w[2]*H0[2].y + w[3]*H0[3].y);
        acc0.z = fmaf(acc0.z, fac, w[0]*H0[0].z + w[1]*H0[1].z + w[2]*H0[2].z + w[3]*H0[3].z);
        acc0.w = fmaf(acc0.w, fac, w[0]*H0[0].w + w[1]*H0[1].w + w[2]*H0[2].w + w[3]*H0[3].w);
        acc1.x = fmaf(acc1.x, fac, w[0]*H1[0].x + w[1]*H1[1].x + w[2]*H1[2].x + w[3]*H1[3].x);
        acc1.y = fmaf(acc1.y, fac, w[0]*H1[0].y + w[1]*H1[1].y + w[2]*H1[2].y + w[3]*H1[3].y);
        acc1.z = fmaf(acc1.z, fac, w[0]*H1[0].z + w[1]*H1[1].z + w[2]*H1[2].z + w[3]*H1[3].z);
        acc1.w = fmaf(acc1.w, fac, w[0]*H1[0].w + w[1]*H1[1].w + w[2]*H1[2].w + w[3]*H1[3].w);
        m = nm;
    }

    for (; k < cnt; k++) {
        const int sv = __ldg(&sp[k]);
        const float4* hp = (const float4*)&g_hs1[(size_t)sv * HH + lane * 8];
        const float4 h0 = __ldg(hp);
        const float4 h1 = __ldg(hp + 1);

        float p = lrelu(h0.x + hd0.x) * a0.x + lrelu(h0.y + hd0.y) * a0.y
                + lrelu(h0.z + hd0.z) * a0.z + lrelu(h0.w + hd0.w) * a0.w
                + lrelu(h1.x + hd1.x) * a1.x + lrelu(h1.y + hd1.y) * a1.y
                + lrelu(h1.z + hd1.z) * a1.z + lrelu(h1.w + hd1.w) * a1.w;
        p += __shfl_xor_sync(0xffffffffu, p, 4);
        p += __shfl_xor_sync(0xffffffffu, p, 2);
        p += __shfl_xor_sync(0xffffffffu, p, 1);

        const float nm  = fmaxf(m, p);
        const float fac = __expf(m - nm);
        const float w   = __expf(p - nm);
        s = fmaf(s, fac, w);
        acc0.x = fmaf(acc0.x, fac, w * h0.x);  acc0.y = fmaf(acc0.y, fac, w * h0.y);
        acc0.z = fmaf(acc0.z, fac, w * h0.z);  acc0.w = fmaf(acc0.w, fac, w * h0.w);
        acc1.x = fmaf(acc1.x, fac, w * h1.x);  acc1.y = fmaf(acc1.y, fac, w * h1.y);
        acc1.z = fmaf(acc1.z, fac, w * h1.z);  acc1.w = fmaf(acc1.w, fac, w * h1.w);
        m = nm;
    }

    const float inv = (s > 0.f) ? (1.f / s) : 0.f;
    float o[8] = { acc0.x * inv, acc0.y * inv, acc0.z * inv, acc0.w * inv,
                   acc1.x * inv, acc1.y * inv, acc1.z * inv, acc1.w * inv };

    // fused: ELU + layer-2 projections ([256] -> 2, two weight matrices)
    float s0 = 0.f, s1 = 0.f, d0 = 0.f, d1 = 0.f;
#pragma unroll
    for (int j = 0; j < 8; j++) {
        const float oj = (o[j] > 0.f) ? o[j] : expm1f(o[j]);   // ELU
        const int dix = lane * 8 + j;
        const float2 ws = __ldg((const float2*)&W2s[dix * 2]);
        const float2 wd = __ldg((const float2*)&W2d[dix * 2]);
        s0 += oj * ws.x;  s1 += oj * ws.y;
        d0 += oj * wd.x;  d1 += oj * wd.y;
    }
#pragma unroll
    for (int off = 16; off > 0; off >>= 1) {
        s0 += __shfl_xor_sync(0xffffffffu, s0, off);
        s1 += __shfl_xor_sync(0xffffffffu, s1, off);
        d0 += __shfl_xor_sync(0xffffffffu, d0, off);
        d1 += __shfl_xor_sync(0xffffffffu, d1, off);
    }
    if (lane == 0) {
        g_hs2[warp] = make_float2(s0 + __ldg(&b2s[0]), s1 + __ldg(&b2s[1]));
        g_hd2[warp] = make_float2(d0 + __ldg(&b2d[0]), d1 + __ldg(&b2d[1]));
    }
}

// ---------------- layer-2 edge phase: one thread per dst node, 4-edge batch ----------------
__global__ void edge2_kernel(const float* __restrict__ attn2,
                             float* __restrict__ out, int n)
{
    const int node = blockIdx.x * blockDim.x + threadIdx.x;
    if (node >= n) return;

    const float2 hd = g_hd2[node];
    const float ax = __ldg(&attn2[0]);
    const float ay = __ldg(&attn2[1]);

    const int beg = g_rowptr[node];
    const int cnt = g_rowptr[node + 1] - beg;
    const int* sp = g_srcs + beg;

    float m = __int_as_float(0xff800000);
    float s = 0.f, a0 = 0.f, a1 = 0.f;

    int k = 0;
    for (; k + 4 <= cnt; k += 4) {
        float2 hs[4];
#pragma unroll
        for (int j = 0; j < 4; j++) hs[j] = __ldg(&g_hs2[__ldg(&sp[k + j])]);
        float p[4];
#pragma unroll
        for (int j = 0; j < 4; j++)
            p[j] = lrelu(hs[j].x + hd.x) * ax + lrelu(hs[j].y + hd.y) * ay;

        const float nm = fmaxf(fmaxf(fmaxf(p[0], p[1]), fmaxf(p[2], p[3])), m);
        const float fac = __expf(m - nm);
        float w[4];
#pragma unroll
        for (int j = 0; j < 4; j++) w[j] = __expf(p[j] - nm);

        s  = fmaf(s,  fac, w[0] + w[1] + w[2] + w[3]);
        a0 = fmaf(a0, fac, w[0]*hs[0].x + w[1]*hs[1].x + w[2]*hs[2].x + w[3]*hs[3].x);
        a1 = fmaf(a1, fac, w[0]*hs[0].y + w[1]*hs[1].y + w[2]*hs[2].y + w[3]*hs[3].y);
        m = nm;
    }
    for (; k < cnt; k++) {
        const float2 hs = __ldg(&g_hs2[__ldg(&sp[k])]);
        const float p = lrelu(hs.x + hd.x) * ax + lrelu(hs.y + hd.y) * ay;
        const float nm  = fmaxf(m, p);
        const float fac = __expf(m - nm);
        const float w   = __expf(p - nm);
        s  = fmaf(s,  fac, w);
        a0 = fmaf(a0, fac, w * hs.x);
        a1 = fmaf(a1, fac, w * hs.y);
        m = nm;
    }
    const float inv = (s > 0.f) ? (1.f / s) : 0.f;
    out[(size_t)node * 2 + 0] = a0 * inv;
    out[(size_t)node * 2 + 1] = a1 * inv;
}

// ---------------- launch ----------------
extern "C" void kernel_launch(void* const* d_in, const int* in_sizes, int n_in,
                              void* d_out, int out_size)
{
    const float* feat  = (const float*)d_in[0];
    const int*   src   = (const int*)  d_in[1];
    const int*   dst   = (const int*)  d_in[2];
    const float* W1s   = (const float*)d_in[3];
    const float* b1s   = (const float*)d_in[4];
    const float* W1d   = (const float*)d_in[5];
    const float* b1d   = (const float*)d_in[6];
    const float* attn1 = (const float*)d_in[7];
    const float* W2s   = (const float*)d_in[8];
    const float* b2s   = (const float*)d_in[9];
    const float* W2d   = (const float*)d_in[10];
    const float* b2d   = (const float*)d_in[11];
    const float* attn2 = (const float*)d_in[12];

    const int n = in_sizes[0] / F_IN;
    const int e = in_sizes[1];

    // CSR build + projections. sgemm stays the 4th launch (ncu capture window).
    init_kernel<<<(n + 255) / 256, 256>>>(n);
    count_kernel<<<(e + 255) / 256, 256>>>(dst, e);
    scan_kernel<<<1, 1024>>>(n, e);

    dim3 g1(2, (n + 127) / 128, 2);
    sgemm_kernel<<<g1, 256>>>(feat, W1s, b1s, W1d, b1d, n);

    scatter_kernel<<<(e + 255) / 256, 256>>>(src, dst, e);

    // layer-1 attention + aggregation + ELU + layer-2 GEMV (fused)
    edge1_kernel<<<(n + 7) / 8, 256>>>(attn1, W2s, b2s, W2d, b2d, n);

    // layer-2 attention + aggregation -> output [n,2]
    edge2_kernel<<<(n + 255) / 256, 256>>>(attn2, (float*)d_out, n);
}

// round 7
// speedup vs baseline: 2.2174x; 1.2589x over previous
#include <cuda_runtime.h>
#include <math.h>

#define N_MAX 50000
#define E_MAX 800000
#define F_IN 128
#define HH 256           // HEADS*HID = 4*64
#define NEG_SLOPE 0.2f

// ---------------- scratch (static device, no allocation) ----------------
__device__ __align__(16) float g_hs1[(size_t)N_MAX * HH];
__device__ __align__(16) float g_hd1[(size_t)N_MAX * HH];
__device__ __align__(16) float2 g_hs2[N_MAX];
__device__ __align__(16) float2 g_hd2[N_MAX];
__device__ int g_deg[N_MAX];
__device__ int g_cursor[N_MAX];
__device__ int g_rowptr[N_MAX + 1];
__device__ int g_srcs[E_MAX];     // src node id, grouped by dst (CSR adjacency)

__device__ __forceinline__ float lrelu(float x) {
    return x > 0.f ? x : NEG_SLOPE * x;
}

// cp.async helpers
__device__ __forceinline__ void cp16(unsigned dst_smem, const void* src) {
    asm volatile("cp.async.cg.shared.global [%0], [%1], 16;" :: "r"(dst_smem), "l"(src));
}
__device__ __forceinline__ void cp_commit() {
    asm volatile("cp.async.commit_group;");
}
__device__ __forceinline__ void cp_wait0() {
    asm volatile("cp.async.wait_group 0;");
}

// tf32 helpers
__device__ __forceinline__ unsigned cvt_tf32(float f) {
    unsigned r;
    asm("cvt.rna.tf32.f32 %0, %1;" : "=r"(r) : "f"(f));
    return r;
}
__device__ __forceinline__ void ldmatrix_x4(unsigned& d0, unsigned& d1,
                                            unsigned& d2, unsigned& d3, unsigned addr) {
    asm volatile("ldmatrix.sync.aligned.m8n8.x4.shared.b16 {%0,%1,%2,%3}, [%4];"
                 : "=r"(d0), "=r"(d1), "=r"(d2), "=r"(d3) : "r"(addr));
}
__device__ __forceinline__ void mma_tf32(float* c, const unsigned* a, unsigned b0, unsigned b1) {
    asm volatile("mma.sync.aligned.m16n8k8.row.col.f32.tf32.tf32.f32 "
                 "{%0,%1,%2,%3}, {%4,%5,%6,%7}, {%8,%9}, {%0,%1,%2,%3};"
                 : "+f"(c[0]), "+f"(c[1]), "+f"(c[2]), "+f"(c[3])
                 : "r"(a[0]), "r"(a[1]), "r"(a[2]), "r"(a[3]), "r"(b0), "r"(b1));
}

// ---------------- CSR build ----------------
__global__ void init_kernel(int n) {
    int i = blockIdx.x * blockDim.x + threadIdx.x;
    if (i < n) { g_deg[i] = 0; g_cursor[i] = 0; }
}

__global__ void count_kernel(const int* __restrict__ dst, int e) {
    int i = blockIdx.x * blockDim.x + threadIdx.x;
    if (i < e) atomicAdd(&g_deg[dst[i]], 1);
}

__global__ void scan_kernel(int n, int e) {
    __shared__ int sums[1024];
    int t = threadIdx.x;
    int chunk = (n + 1023) >> 10;
    int b = t * chunk;
    int en = min(b + chunk, n);
    int s = 0;
    for (int i = b; i < en; i++) s += g_deg[i];
    sums[t] = s;
    __syncthreads();
    for (int off = 1; off < 1024; off <<= 1) {
        int v = 0;
        if (t >= off) v = sums[t - off];
        __syncthreads();
        if (t >= off) sums[t] += v;
        __syncthreads();
    }
    int run = (t == 0) ? 0 : sums[t - 1];
    for (int i = b; i < en; i++) { g_rowptr[i] = run; run += g_deg[i]; }
    if (t == 0) g_rowptr[n] = e;
}

__global__ void scatter_kernel(const int* __restrict__ src,
                               const int* __restrict__ dst, int e) {
    int i = blockIdx.x * blockDim.x + threadIdx.x;
    if (i < e) {
        int d = dst[i];
        int pos = g_rowptr[d] + atomicAdd(&g_cursor[d], 1);
        g_srcs[pos] = src[i];
    }
}

// ---------------- layer-1 GEMM via tf32 tensor cores ----------------
// C[n,256] = A[n,128] @ W[128,256] + b.  BM=128, BN=128, BK=16, 256 threads.
// 8 warps as 4x2 -> warp tile 32x64 = 2x8 m16n8k8 mma tiles.
// As: [row][20] padded rows (conflict-free ldmatrix); Bs: [k][136] padded
// rows (8c+g spans all 32 banks -> conflict-free LDS.32 fragments).
#define AP 20
#define BP 136
__global__ __launch_bounds__(256, 2) void sgemm_kernel(
    const float* __restrict__ A,
    const float* __restrict__ Ws, const float* __restrict__ bs,
    const float* __restrict__ Wd, const float* __restrict__ bd,
    int n)
{
    const float* B    = blockIdx.z ? Wd : Ws;
    const float* bias = blockIdx.z ? bd : bs;
    float* C          = blockIdx.z ? g_hd1 : g_hs1;

    const int rowBase = blockIdx.y * 128;
    const int colBase = blockIdx.x * 128;

    __shared__ float As[2][128 * AP];
    __shared__ float Bs[2][16 * BP];

    const int tid  = threadIdx.x;
    const int wid  = tid >> 5;
    const int lane = tid & 31;
    const int warp_m = wid & 3;      // 32-row slice
    const int warp_n = wid >> 2;     // 64-col slice

    float acc[2][8][4];
#pragma unroll
    for (int mt = 0; mt < 2; mt++)
#pragma unroll
        for (int nt = 0; nt < 8; nt++)
#pragma unroll
            for (int r = 0; r < 4; r++) acc[mt][nt][r] = 0.f;

    // ---- staging geometry ----
    // A: thread covers row ar, 16B-chunks c0 and c0+1 (of 4 per row)
    const int ar = tid >> 1;
    const int ac0 = (tid & 1) * 2;
    const int grA = rowBase + ar;
    const bool aok = (grA < n);
    const float* aSrc = A + (size_t)grA * F_IN;
    // B: thread covers k-row bk, 16B-chunks bc0 and bc0+1 (of 32 per row)
    const int bk  = tid >> 4;
    const int bc0 = (tid & 15) * 2;
    const float* bSrc = B + (size_t)bk * HH + colBase;

    const unsigned asBase0 = (unsigned)__cvta_generic_to_shared(&As[0][0]);
    const unsigned asBase1 = (unsigned)__cvta_generic_to_shared(&As[1][0]);
    const unsigned bsBase0 = (unsigned)__cvta_generic_to_shared(&Bs[0][0]);
    const unsigned bsBase1 = (unsigned)__cvta_generic_to_shared(&Bs[1][0]);

    // ---- prologue: stage 0 (kb = 0) ----
    if (aok) {
        cp16(asBase0 + (ar * AP + ac0 * 4) * 4,       aSrc + ac0 * 4);
        cp16(asBase0 + (ar * AP + (ac0 + 1) * 4) * 4, aSrc + (ac0 + 1) * 4);
    }
    cp16(bsBase0 + (bk * BP + bc0 * 4) * 4,       bSrc + bc0 * 4);
    cp16(bsBase0 + (bk * BP + (bc0 + 1) * 4) * 4, bSrc + (bc0 + 1) * 4);
    cp_commit();
    cp_wait0();
    __syncthreads();

    // ldmatrix address components (fixed per thread)
    const int lmRow = warp_m * 32 + (lane & 7) + ((lane >> 3) & 1) * 8;
    const int lmK   = (lane >> 4) * 4;
    // B fragment indices
    const int fn = warp_n * 64 + (lane >> 2);   // + nt*8
    const int fk = lane & 3;                    // + kc*8, +4 for b1

#pragma unroll
    for (int kt = 0; kt < 8; kt++) {
        const int cur = kt & 1;
        const unsigned asCur = cur ? asBase1 : asBase0;
        if (kt < 7) {
            const int kb = (kt + 1) * 16;
            const unsigned asN = (cur ^ 1) ? asBase1 : asBase0;
            const unsigned bsN = (cur ^ 1) ? bsBase1 : bsBase0;
            if (aok) {
                cp16(asN + (ar * AP + ac0 * 4) * 4,       aSrc + kb + ac0 * 4);
                cp16(asN + (ar * AP + (ac0 + 1) * 4) * 4, aSrc + kb + (ac0 + 1) * 4);
            }
            cp16(bsN + (bk * BP + bc0 * 4) * 4,       bSrc + (size_t)kb * HH + bc0 * 4);
            cp16(bsN + (bk * BP + (bc0 + 1) * 4) * 4, bSrc + (size_t)kb * HH + (bc0 + 1) * 4);
            cp_commit();
        }

        const float* bsCur = Bs[cur];
#pragma unroll
        for (int kc = 0; kc < 2; kc++) {
            unsigned a[2][4];
#pragma unroll
            for (int mt = 0; mt < 2; mt++) {
                const unsigned addr = asCur + ((lmRow + mt * 16) * AP + kc * 8 + lmK) * 4;
                ldmatrix_x4(a[mt][0], a[mt][1], a[mt][2], a[mt][3], addr);
            }
#pragma unroll
            for (int mt = 0; mt < 2; mt++)
#pragma unroll
                for (int r = 0; r < 4; r++)
                    a[mt][r] = cvt_tf32(__uint_as_float(a[mt][r]));

            const int kk = kc * 8 + fk;
#pragma unroll
            for (int nt = 0; nt < 8; nt++) {
                const float b0f = bsCur[kk * BP + fn + nt * 8];
                const float b1f = bsCur[(kk + 4) * BP + fn + nt * 8];
                const unsigned b0 = cvt_tf32(b0f);
                const unsigned b1 = cvt_tf32(b1f);
                mma_tf32(acc[0][nt], a[0], b0, b1);
                mma_tf32(acc[1][nt], a[1], b0, b1);
            }
        }

        if (kt < 7) {
            cp_wait0();
            __syncthreads();
        }
    }

    // ---- epilogue: add bias, store float2 pairs ----
    float2 bv[8];
#pragma unroll
    for (int nt = 0; nt < 8; nt++) {
        const int col = colBase + warp_n * 64 + nt * 8 + (lane & 3) * 2;
        bv[nt] = __ldg((const float2*)&bias[col]);
    }
    const int g = lane >> 2;
#pragma unroll
    for (int mt = 0; mt < 2; mt++) {
        const int r0 = rowBase + warp_m * 32 + mt * 16 + g;
        const int r1 = r0 + 8;
#pragma unroll
        for (int nt = 0; nt < 8; nt++) {
            const int col = colBase + warp_n * 64 + nt * 8 + (lane & 3) * 2;
            if (r0 < n) {
                float2 v = make_float2(acc[mt][nt][0] + bv[nt].x,
                                       acc[mt][nt][1] + bv[nt].y);
                *(float2*)&C[(size_t)r0 * HH + col] = v;
            }
            if (r1 < n) {
                float2 v = make_float2(acc[mt][nt][2] + bv[nt].x,
                                       acc[mt][nt][3] + bv[nt].y);
                *(float2*)&C[(size_t)r1 * HH + col] = v;
            }
        }
    }
}

// ---------------- layer-1 edge phase, 4-edge batched online softmax ----------------
__global__ __launch_bounds__(256) void edge1_kernel(
    const float* __restrict__ attn1,
    const float* __restrict__ W2s, const float* __restrict__ b2s,
    const float* __restrict__ W2d, const float* __restrict__ b2d,
    int n)
{
    const int warp = (blockIdx.x * blockDim.x + threadIdx.x) >> 5;
    const int lane = threadIdx.x & 31;
    if (warp >= n) return;

    const float4* hdp = (const float4*)&g_hd1[(size_t)warp * HH + lane * 8];
    const float4 hd0 = hdp[0], hd1 = hdp[1];
    const float4* ap = (const float4*)(attn1 + lane * 8);
    const float4 a0 = __ldg(ap), a1 = __ldg(ap + 1);

    const int beg = g_rowptr[warp];
    const int cnt = g_rowptr[warp + 1] - beg;
    const int* sp = g_srcs + beg;

    float m = __int_as_float(0xff800000);   // -inf
    float s = 0.f;
    float4 acc0 = make_float4(0, 0, 0, 0);
    float4 acc1 = make_float4(0, 0, 0, 0);

    int k = 0;
    for (; k + 4 <= cnt; k += 4) {
        int sv[4];
#pragma unroll
        for (int j = 0; j < 4; j++) sv[j] = __ldg(&sp[k + j]);

        float4 H0[4], H1[4];
#pragma unroll
        for (int j = 0; j < 4; j++) {
            const float4* hp = (const float4*)&g_hs1[(size_t)sv[j] * HH + lane * 8];
            H0[j] = __ldg(hp);
            H1[j] = __ldg(hp + 1);
        }

        float p[4];
#pragma unroll
        for (int j = 0; j < 4; j++) {
            p[j] = lrelu(H0[j].x + hd0.x) * a0.x + lrelu(H0[j].y + hd0.y) * a0.y
                 + lrelu(H0[j].z + hd0.z) * a0.z + lrelu(H0[j].w + hd0.w) * a0.w
                 + lrelu(H1[j].x + hd1.x) * a1.x + lrelu(H1[j].y + hd1.y) * a1.y
                 + lrelu(H1[j].z + hd1.z) * a1.z + lrelu(H1[j].w + hd1.w) * a1.w;
        }
#pragma unroll
        for (int j = 0; j < 4; j++) p[j] += __shfl_xor_sync(0xffffffffu, p[j], 4);
#pragma unroll
        for (int j = 0; j < 4; j++) p[j] += __shfl_xor_sync(0xffffffffu, p[j], 2);
#pragma unroll
        for (int j = 0; j < 4; j++) p[j] += __shfl_xor_sync(0xffffffffu, p[j], 1);

        const float nm = fmaxf(fmaxf(fmaxf(p[0], p[1]), fmaxf(p[2], p[3])), m);
        const float fac = __expf(m - nm);
        float w[4];
#pragma unroll
        for (int j = 0; j < 4; j++) w[j] = __expf(p[j] - nm);

        s = fmaf(s, fac, w[0] + w[1] + w[2] + w[3]);
        acc0.x = fmaf(acc0.x, fac, w[0]*H0[0].x + w[1]*H0[1].x + w[2]*H0[2].x + w[3]*H0[3].x);
        acc0.y = fmaf(acc0.y, fac, w[0]*H0[0].y + w[1]*H0[1].y + w[2]*H0[2].y + w[3]*H0[3].y);
        acc0.z = fmaf(acc0.z, fac, w[0]*H0[0].z + w[1]*H0[1].z + w[2]*H0[2].z + w[3]*H0[3].z);
        acc0.w = fmaf(acc0.w, fac, w[0]*H0[0].w + w[1]*H0[1].w + w[2]*H0[2].w + w[3]*H0[3].w);
        acc1.x = fmaf(acc1.x, fac, w[0]*H1[0].x + w[1]*H1[1].x + w[2]*H1[2].x + w[3]*H1[3].x);
        acc1.y = fmaf(acc1.y, fac, w[0]*H1[0].y + w[1]*H1[1].y + w[2]*H1[2].y + w[3]*H1[3].y);
        acc1.z = fmaf(acc1.z, fac, w[0]*H1[0].z + w[1]*H1[1].z + w[2]*H1[2].z + w[3]*H1[3].z);
        acc1.w = fmaf(acc1.w, fac, w[0]*H1[0].w + w[1]*H1[1].w + w[2]*H1[2].w + w[3]*H1[3].w);
        m = nm;
    }

    for (; k < cnt; k++) {
        const int sv = __ldg(&sp[k]);
        const float4* hp = (const float4*)&g_hs1[(size_t)sv * HH + lane * 8];
        const float4 h0 = __ldg(hp);
        const float4 h1 = __ldg(hp + 1);

        float p = lrelu(h0.x + hd0.x) * a0.x + lrelu(h0.y + hd0.y) * a0.y
                + lrelu(h0.z + hd0.z) * a0.z + lrelu(h0.w + hd0.w) * a0.w
                + lrelu(h1.x + hd1.x) * a1.x + lrelu(h1.y + hd1.y) * a1.y
                + lrelu(h1.z + hd1.z) * a1.z + lrelu(h1.w + hd1.w) * a1.w;
        p += __shfl_xor_sync(0xffffffffu, p, 4);
        p += __shfl_xor_sync(0xffffffffu, p, 2);
        p += __shfl_xor_sync(0xffffffffu, p, 1);

        const float nm  = fmaxf(m, p);
        const float fac = __expf(m - nm);
        const float w   = __expf(p - nm);
        s = fmaf(s, fac, w);
        acc0.x = fmaf(acc0.x, fac, w * h0.x);  acc0.y = fmaf(acc0.y, fac, w * h0.y);
        acc0.z = fmaf(acc0.z, fac, w * h0.z);  acc0.w = fmaf(acc0.w, fac, w * h0.w);
        acc1.x = fmaf(acc1.x, fac, w * h1.x);  acc1.y = fmaf(acc1.y, fac, w * h1.y);
        acc1.z = fmaf(acc1.z, fac, w * h1.z);  acc1.w = fmaf(acc1.w, fac, w * h1.w);
        m = nm;
    }

    const float inv = (s > 0.f) ? (1.f / s) : 0.f;
    float o[8] = { acc0.x * inv, acc0.y * inv, acc0.z * inv, acc0.w * inv,
                   acc1.x * inv, acc1.y * inv, acc1.z * inv, acc1.w * inv };

    // fused: ELU + layer-2 projections ([256] -> 2, two weight matrices)
    float s0 = 0.f, s1 = 0.f, d0 = 0.f, d1 = 0.f;
#pragma unroll
    for (int j = 0; j < 8; j++) {
        const float oj = (o[j] > 0.f) ? o[j] : expm1f(o[j]);   // ELU
        const int dix = lane * 8 + j;
        const float2 ws = __ldg((const float2*)&W2s[dix * 2]);
        const float2 wd = __ldg((const float2*)&W2d[dix * 2]);
        s0 += oj * ws.x;  s1 += oj * ws.y;
        d0 += oj * wd.x;  d1 += oj * wd.y;
    }
#pragma unroll
    for (int off = 16; off > 0; off >>= 1) {
        s0 += __shfl_xor_sync(0xffffffffu, s0, off);
        s1 += __shfl_xor_sync(0xffffffffu, s1, off);
        d0 += __shfl_xor_sync(0xffffffffu, d0, off);
        d1 += __shfl_xor_sync(0xffffffffu, d1, off);
    }
    if (lane == 0) {
        g_hs2[warp] = make_float2(s0 + __ldg(&b2s[0]), s1 + __ldg(&b2s[1]));
        g_hd2[warp] = make_float2(d0 + __ldg(&b2d[0]), d1 + __ldg(&b2d[1]));
    }
}

// ---------------- layer-2 edge phase: one thread per dst node, 4-edge batch ----------------
__global__ void edge2_kernel(const float* __restrict__ attn2,
                             float* __restrict__ out, int n)
{
    const int node = blockIdx.x * blockDim.x + threadIdx.x;
    if (node >= n) return;

    const float2 hd = g_hd2[node];
    const float ax = __ldg(&attn2[0]);
    const float ay = __ldg(&attn2[1]);

    const int beg = g_rowptr[node];
    const int cnt = g_rowptr[node + 1] - beg;
    const int* sp = g_srcs + beg;

    float m = __int_as_float(0xff800000);
    float s = 0.f, a0 = 0.f, a1 = 0.f;

    int k = 0;
    for (; k + 4 <= cnt; k += 4) {
        float2 hs[4];
#pragma unroll
        for (int j = 0; j < 4; j++) hs[j] = __ldg(&g_hs2[__ldg(&sp[k + j])]);
        float p[4];
#pragma unroll
        for (int j = 0; j < 4; j++)
            p[j] = lrelu(hs[j].x + hd.x) * ax + lrelu(hs[j].y + hd.y) * ay;

        const float nm = fmaxf(fmaxf(fmaxf(p[0], p[1]), fmaxf(p[2], p[3])), m);
        const float fac = __expf(m - nm);
        float w[4];
#pragma unroll
        for (int j = 0; j < 4; j++) w[j] = __expf(p[j] - nm);

        s  = fmaf(s,  fac, w[0] + w[1] + w[2] + w[3]);
        a0 = fmaf(a0, fac, w[0]*hs[0].x + w[1]*hs[1].x + w[2]*hs[2].x + w[3]*hs[3].x);
        a1 = fmaf(a1, fac, w[0]*hs[0].y + w[1]*hs[1].y + w[2]*hs[2].y + w[3]*hs[3].y);
        m = nm;
    }
    for (; k < cnt; k++) {
        const float2 hs = __ldg(&g_hs2[__ldg(&sp[k])]);
        const float p = lrelu(hs.x + hd.x) * ax + lrelu(hs.y + hd.y) * ay;
        const float nm  = fmaxf(m, p);
        const float fac = __expf(m - nm);
        const float w   = __expf(p - nm);
        s  = fmaf(s,  fac, w);
        a0 = fmaf(a0, fac, w * hs.x);
        a1 = fmaf(a1, fac, w * hs.y);
        m = nm;
    }
    const float inv = (s > 0.f) ? (1.f / s) : 0.f;
    out[(size_t)node * 2 + 0] = a0 * inv;
    out[(size_t)node * 2 + 1] = a1 * inv;
}

// ---------------- launch ----------------
extern "C" void kernel_launch(void* const* d_in, const int* in_sizes, int n_in,
                              void* d_out, int out_size)
{
    const float* feat  = (const float*)d_in[0];
    const int*   src   = (const int*)  d_in[1];
    const int*   dst   = (const int*)  d_in[2];
    const float* W1s   = (const float*)d_in[3];
    const float* b1s   = (const float*)d_in[4];
    const float* W1d   = (const float*)d_in[5];
    const float* b1d   = (const float*)d_in[6];
    const float* attn1 = (const float*)d_in[7];
    const float* W2s   = (const float*)d_in[8];
    const float* b2s   = (const float*)d_in[9];
    const float* W2d   = (const float*)d_in[10];
    const float* b2d   = (const float*)d_in[11];
    const float* attn2 = (const float*)d_in[12];

    const int n = in_sizes[0] / F_IN;
    const int e = in_sizes[1];

    // CSR build + projections. sgemm stays the 4th launch (ncu capture window).
    init_kernel<<<(n + 255) / 256, 256>>>(n);
    count_kernel<<<(e + 255) / 256, 256>>>(dst, e);
    scan_kernel<<<1, 1024>>>(n, e);

    dim3 g1(2, (n + 127) / 128, 2);
    sgemm_kernel<<<g1, 256>>>(feat, W1s, b1s, W1d, b1d, n);

    scatter_kernel<<<(e + 255) / 256, 256>>>(src, dst, e);

    // layer-1 attention + aggregation + ELU + layer-2 GEMV (fused)
    edge1_kernel<<<(n + 7) / 8, 256>>>(attn1, W2s, b2s, W2d, b2d, n);

    // layer-2 attention + aggregation -> output [n,2]
    edge2_kernel<<<(n + 255) / 256, 256>>>(attn2, (float*)d_out, n);
}